// round 9
// baseline (speedup 1.0000x reference)
#include <cuda_runtime.h>
#include <cuda_fp16.h>
#include <math.h>
#include <stdint.h>

#define BW    4096
#define NTOK  49
#define DIM   192
#define HEADS 6
#define HD    32
#define HIDDEN 768
#define MROWS (BW * NTOK)   // 200704

// ---------------------------------------------------------------------------
// Scratch (allocation-free, __device__ globals)
// ---------------------------------------------------------------------------
__device__ __half g_act192[(size_t)MROWS * DIM];
__device__ __half g_qkvh[(size_t)MROWS * 3 * DIM];
__device__ __half g_hid[(size_t)MROWS * HIDDEN];

__device__ __half g_wqkv[3 * DIM * DIM];
__device__ __half g_wprj[DIM * DIM];
__device__ __half g_wfc1[DIM * HIDDEN];
__device__ __half g_wfc2[HIDDEN * DIM];
__device__ float  g_bias[HEADS * NTOK * NTOK];

// ---------------------------------------------------------------------------
// helpers
// ---------------------------------------------------------------------------
__device__ __forceinline__ uint32_t smem_u32(const void* p) {
    uint32_t a;
    asm("{ .reg .u64 t; cvta.to.shared.u64 t, %1; cvt.u32.u64 %0, t; }" : "=r"(a) : "l"(p));
    return a;
}
__device__ __forceinline__ void cpa16(uint32_t dst, const void* src) {
    asm volatile("cp.async.cg.shared.global [%0], [%1], 16;" :: "r"(dst), "l"(src));
}
__device__ __forceinline__ void cp_commit() {
    asm volatile("cp.async.commit_group;" ::: "memory");
}
__device__ __forceinline__ void cp_wait2() {
    asm volatile("cp.async.wait_group 2;" ::: "memory");
}
__device__ __forceinline__ void ldmx4(uint32_t* r, uint32_t addr) {
    asm volatile("ldmatrix.sync.aligned.m8n8.x4.shared.b16 {%0,%1,%2,%3}, [%4];"
                 : "=r"(r[0]), "=r"(r[1]), "=r"(r[2]), "=r"(r[3]) : "r"(addr));
}
__device__ __forceinline__ void mma_f16(float* c, const uint32_t* a,
                                        uint32_t b0, uint32_t b1) {
    asm volatile(
        "mma.sync.aligned.m16n8k16.row.col.f32.f16.f16.f32 "
        "{%0,%1,%2,%3}, {%4,%5,%6,%7}, {%8,%9}, {%0,%1,%2,%3};"
        : "+f"(c[0]), "+f"(c[1]), "+f"(c[2]), "+f"(c[3])
        : "r"(a[0]), "r"(a[1]), "r"(a[2]), "r"(a[3]), "r"(b0), "r"(b1));
}

// ---------------------------------------------------------------------------
// prep kernels
// ---------------------------------------------------------------------------
__global__ void prep_w(const float* __restrict__ W, __half* __restrict__ Wt,
                       int K, int N)
{
    int idx = blockIdx.x * blockDim.x + threadIdx.x;
    if (idx >= K * N) return;
    int k = idx / N, n = idx - k * N;
    Wt[(size_t)n * K + k] = __float2half_rn(W[idx]);
}

__global__ void prep_misc(const float* __restrict__ Wp, __half* __restrict__ Wpt,
                          const float* __restrict__ table, const int* __restrict__ ridx,
                          float* __restrict__ biasg)
{
    const int NW = DIM * DIM;
    const int NB = HEADS * NTOK * NTOK;
    for (int idx = blockIdx.x * blockDim.x + threadIdx.x; idx < NW + NB;
         idx += gridDim.x * blockDim.x) {
        if (idx < NW) {
            int k = idx / DIM, n = idx - k * DIM;
            Wpt[(size_t)n * DIM + k] = __float2half_rn(Wp[idx]);
        } else {
            int i = idx - NW;
            int h = i / (NTOK * NTOK), ij = i % (NTOK * NTOK);
            biasg[i] = table[ridx[ij] * HEADS + h];
        }
    }
}

__global__ void prep_fc(const float* __restrict__ W1, __half* __restrict__ W1t,
                        const float* __restrict__ W2, __half* __restrict__ W2t)
{
    const int N1 = DIM * HIDDEN;
    for (int idx = blockIdx.x * blockDim.x + threadIdx.x; idx < 2 * N1;
         idx += gridDim.x * blockDim.x) {
        if (idx < N1) {
            int k = idx / HIDDEN, n = idx - k * HIDDEN;
            W1t[(size_t)n * DIM + k] = __float2half_rn(W1[idx]);
        } else {
            int i = idx - N1;
            int k = i / DIM, n = i - k * DIM;
            W2t[(size_t)n * HIDDEN + k] = __float2half_rn(W2[i]);
        }
    }
}

// ---------------------------------------------------------------------------
// LayerNorm -> fp16
// ---------------------------------------------------------------------------
__global__ __launch_bounds__(DIM) void ln_kernel(
    const float* __restrict__ x, const float* __restrict__ g,
    const float* __restrict__ b, __half* __restrict__ o)
{
    int row = blockIdx.x;
    int t = threadIdx.x;
    float v = x[(size_t)row * DIM + t];
    float s = v, s2 = v * v;
    #pragma unroll
    for (int of = 16; of > 0; of >>= 1) {
        s  += __shfl_down_sync(0xffffffffu, s,  of);
        s2 += __shfl_down_sync(0xffffffffu, s2, of);
    }
    __shared__ float r0[6], r1[6];
    if ((t & 31) == 0) { r0[t >> 5] = s; r1[t >> 5] = s2; }
    __syncthreads();
    if (t == 0) {
        float a = 0.f, c = 0.f;
        #pragma unroll
        for (int i = 0; i < 6; i++) { a += r0[i]; c += r1[i]; }
        r0[0] = a * (1.0f / DIM); r1[0] = c * (1.0f / DIM);
    }
    __syncthreads();
    float mu = r0[0];
    float var = r1[0] - mu * mu;
    float y = (v - mu) * rsqrtf(var + 1e-5f) * g[t] + b[t];
    o[(size_t)row * DIM + t] = __float2half_rn(y);
}

// ---------------------------------------------------------------------------
// fp16 HMMA GEMM: C = A @ W^T (+epilogue)
// Block tile 128x192, 256 threads = 8 warps (2 M x 4 N), warp tile 64x48,
// K-step 32, 4-stage cp.async pipeline, XOR-swizzled ldmatrix.
// EPI: 0 -> fp16 Ch | 1 bias+res -> fp32 Cf | 2 bias+gelu -> fp16 Ch
//      3 bias+res -> fp32 Cf + fused LN -> fp16 Ch (needs N_TOTAL==192)
// ---------------------------------------------------------------------------
#define STAGE   20480u  // A 8K + B 12K
#define O_B     8192u
#define NSTAGE  4
#define GEMM_SMEM (NSTAGE * 20480)

template <int N_TOTAL, int K_TOTAL, int EPI>
__global__ __launch_bounds__(256, 1) void tc_gemm(
    const __half* __restrict__ A, const __half* __restrict__ B,
    const float* __restrict__ bias, const float* __restrict__ res,
    float* __restrict__ Cf, __half* __restrict__ Ch,
    const float* __restrict__ lng, const float* __restrict__ lnb)
{
    constexpr int KSTEPS = K_TOTAL / 32;

    extern __shared__ char smem[];
    __shared__ float s_red[128 * 8];
    uint32_t sb = smem_u32(smem);
    int tid = threadIdx.x, lane = tid & 31, wid = tid >> 5;
    int wm = wid & 1, wn = wid >> 1;          // 2 x 4 warp grid
    size_t rowbase = (size_t)blockIdx.y * 128;
    int colbase = blockIdx.x * 192;

    auto load_stage = [&](int s) {
        uint32_t base = sb + (uint32_t)(s % NSTAGE) * STAGE;
        // A: 128 rows x 4 chunks = 512 -> 2 per thread
        #pragma unroll
        for (int j = 0; j < 2; j++) {
            int i = tid + j * 256;
            int r = i >> 2, kg = i & 3;
            uint32_t soff = r * 64 + ((kg ^ (r & 3)) << 4);
            cpa16(base + soff, A + (rowbase + r) * K_TOTAL + s * 32 + kg * 8);
        }
        // B: 192 rows x 4 chunks = 768 -> 3 per thread
        #pragma unroll
        for (int j = 0; j < 3; j++) {
            int i = tid + j * 256;
            int r = i >> 2, kg = i & 3;
            uint32_t soff = r * 64 + ((kg ^ (r & 3)) << 4);
            cpa16(base + O_B + soff, B + (size_t)(colbase + r) * K_TOTAL + s * 32 + kg * 8);
        }
    };

    uint32_t aoff[4][2], boff[3][2];
    #pragma unroll
    for (int mt = 0; mt < 4; mt++)
        #pragma unroll
        for (int kk = 0; kk < 2; kk++) {
            int ra = wm * 64 + mt * 16 + (lane & 15);
            int kga = kk * 2 + (lane >> 4);
            aoff[mt][kk] = ra * 64 + ((kga ^ (ra & 3)) << 4);
        }
    #pragma unroll
    for (int np = 0; np < 3; np++)
        #pragma unroll
        for (int kk = 0; kk < 2; kk++) {
            int nb = wn * 48 + np * 16 + (lane & 7) + ((lane >> 4) << 3);
            int kgb = kk * 2 + ((lane >> 3) & 1);
            boff[np][kk] = nb * 64 + ((kgb ^ (nb & 3)) << 4);
        }

    float acc[4][6][4] = {};

    load_stage(0); cp_commit();
    load_stage(1); cp_commit();
    load_stage(2); cp_commit();

    for (int s = 0; s < KSTEPS; s++) {
        cp_wait2();
        __syncthreads();
        uint32_t base = sb + (uint32_t)(s % NSTAGE) * STAGE;
        #pragma unroll
        for (int kk = 0; kk < 2; kk++) {
            uint32_t ah[4][4];
            #pragma unroll
            for (int mt = 0; mt < 4; mt++) ldmx4(ah[mt], base + aoff[mt][kk]);
            #pragma unroll
            for (int np = 0; np < 3; np++) {
                uint32_t bf[4];
                ldmx4(bf, base + O_B + boff[np][kk]);
                #pragma unroll
                for (int mt = 0; mt < 4; mt++) {
                    mma_f16(acc[mt][np * 2],     ah[mt], bf[0], bf[1]);
                    mma_f16(acc[mt][np * 2 + 1], ah[mt], bf[2], bf[3]);
                }
            }
        }
        if (s + 3 < KSTEPS) load_stage(s + 3);
        cp_commit();
    }

    // ---- epilogue ----
    if (EPI == 3) {
        float psum[4][2] = {}, psq[4][2] = {};
        #pragma unroll
        for (int mt = 0; mt < 4; mt++)
            #pragma unroll
            for (int nt = 0; nt < 6; nt++) {
                int c = colbase + wn * 48 + nt * 8 + (lane & 3) * 2;
                #pragma unroll
                for (int half = 0; half < 2; half++) {
                    size_t row = rowbase + wm * 64 + mt * 16 + (lane >> 2) + half * 8;
                    float v0 = acc[mt][nt][half * 2]     + bias[c];
                    float v1 = acc[mt][nt][half * 2 + 1] + bias[c + 1];
                    const float2 rv = *(const float2*)(res + row * N_TOTAL + c);
                    v0 += rv.x; v1 += rv.y;
                    acc[mt][nt][half * 2] = v0;
                    acc[mt][nt][half * 2 + 1] = v1;
                    psum[mt][half] += v0 + v1;
                    psq[mt][half]  += v0 * v0 + v1 * v1;
                }
            }
        #pragma unroll
        for (int o = 1; o <= 2; o <<= 1)
            #pragma unroll
            for (int mt = 0; mt < 4; mt++)
                #pragma unroll
                for (int half = 0; half < 2; half++) {
                    psum[mt][half] += __shfl_xor_sync(0xffffffffu, psum[mt][half], o);
                    psq[mt][half]  += __shfl_xor_sync(0xffffffffu, psq[mt][half],  o);
                }
        if ((lane & 3) == 0) {
            #pragma unroll
            for (int mt = 0; mt < 4; mt++)
                #pragma unroll
                for (int half = 0; half < 2; half++) {
                    int lrow = wm * 64 + mt * 16 + (lane >> 2) + half * 8;
                    s_red[lrow * 8 + wn * 2]     = psum[mt][half];
                    s_red[lrow * 8 + wn * 2 + 1] = psq[mt][half];
                }
        }
        __syncthreads();
        float mu[4][2], rs[4][2];
        #pragma unroll
        for (int mt = 0; mt < 4; mt++)
            #pragma unroll
            for (int half = 0; half < 2; half++) {
                int lrow = wm * 64 + mt * 16 + (lane >> 2) + half * 8;
                float S = 0.f, Q = 0.f;
                #pragma unroll
                for (int w = 0; w < 4; w++) {
                    S += s_red[lrow * 8 + w * 2];
                    Q += s_red[lrow * 8 + w * 2 + 1];
                }
                float m = S * (1.0f / N_TOTAL);
                float var = Q * (1.0f / N_TOTAL) - m * m;
                mu[mt][half] = m;
                rs[mt][half] = rsqrtf(var + 1e-5f);
            }
        #pragma unroll
        for (int mt = 0; mt < 4; mt++)
            #pragma unroll
            for (int nt = 0; nt < 6; nt++) {
                int c = colbase + wn * 48 + nt * 8 + (lane & 3) * 2;
                float g0 = lng[c], g1 = lng[c + 1];
                float b0 = lnb[c], b1 = lnb[c + 1];
                #pragma unroll
                for (int half = 0; half < 2; half++) {
                    size_t row = rowbase + wm * 64 + mt * 16 + (lane >> 2) + half * 8;
                    float v0 = acc[mt][nt][half * 2];
                    float v1 = acc[mt][nt][half * 2 + 1];
                    float2 ov; ov.x = v0; ov.y = v1;
                    *(float2*)(Cf + row * N_TOTAL + c) = ov;
                    float n0 = (v0 - mu[mt][half]) * rs[mt][half] * g0 + b0;
                    float n1 = (v1 - mu[mt][half]) * rs[mt][half] * g1 + b1;
                    __half2 hv; hv.x = __float2half_rn(n0); hv.y = __float2half_rn(n1);
                    *(__half2*)(Ch + row * N_TOTAL + c) = hv;
                }
            }
    } else {
        #pragma unroll
        for (int mt = 0; mt < 4; mt++) {
            size_t rbase = rowbase + wm * 64 + mt * 16 + (lane >> 2);
            #pragma unroll
            for (int nt = 0; nt < 6; nt++) {
                int c = colbase + wn * 48 + nt * 8 + (lane & 3) * 2;
                #pragma unroll
                for (int half = 0; half < 2; half++) {
                    size_t row = rbase + half * 8;
                    float v0 = acc[mt][nt][half * 2];
                    float v1 = acc[mt][nt][half * 2 + 1];
                    if (EPI >= 1) { v0 += bias[c]; v1 += bias[c + 1]; }
                    if (EPI == 2) {
                        v0 = 0.5f * v0 * (1.0f + erff(v0 * 0.70710678118654752f));
                        v1 = 0.5f * v1 * (1.0f + erff(v1 * 0.70710678118654752f));
                    }
                    if (EPI == 1) {
                        const float2 rv = *(const float2*)(res + row * N_TOTAL + c);
                        float2 ov; ov.x = v0 + rv.x; ov.y = v1 + rv.y;
                        *(float2*)(Cf + row * N_TOTAL + c) = ov;
                    } else {
                        __half2 hv; hv.x = __float2half_rn(v0); hv.y = __float2half_rn(v1);
                        *(__half2*)(Ch + row * N_TOTAL + c) = hv;
                    }
                }
            }
        }
    }
}

// ---------------------------------------------------------------------------
// Tensor-core window attention
// ---------------------------------------------------------------------------
#define SST 65
__global__ __launch_bounds__(128) void attn_kernel(
    const __half* __restrict__ qkv, const float* __restrict__ bias,
    __half* __restrict__ out)
{
    int b = blockIdx.x / HEADS;
    int h = blockIdx.x % HEADS;
    int tid = threadIdx.x, lane = tid & 31, wid = tid >> 5;

    __shared__ __half sQ[64 * 32], sK[64 * 32], sVt[32 * 64], sP[64 * 64];
    __shared__ float sS[64 * SST];

    for (int i = tid; i < 256; i += 128) {
        ((uint4*)sQ)[i]  = make_uint4(0, 0, 0, 0);
        ((uint4*)sK)[i]  = make_uint4(0, 0, 0, 0);
        ((uint4*)sVt)[i] = make_uint4(0, 0, 0, 0);
    }
    for (int i = tid; i < 512; i += 128) ((uint4*)sP)[i] = make_uint4(0, 0, 0, 0);
    __syncthreads();

    const __half* base = qkv + (size_t)b * NTOK * (3 * DIM);
    for (int idx = tid; idx < NTOK * HD / 4; idx += 128) {
        int n = idx >> 3, dc = idx & 7;
        int d = dc * 4;
        const __half* tp = base + n * (3 * DIM) + h * HD + d;
        uint2 qv = *(const uint2*)tp;
        uint2 kv = *(const uint2*)(tp + DIM);
        uint2 vv = *(const uint2*)(tp + 2 * DIM);
        uint32_t qoff = n * 64 + ((((d >> 3) ^ (n & 3))) << 4) + (d & 7) * 2;
        *(uint2*)((char*)sQ + qoff) = qv;
        *(uint2*)((char*)sK + qoff) = kv;
        const __half* vp = (const __half*)&vv;
        #pragma unroll
        for (int e = 0; e < 4; e++) {
            int dd = d + e;
            uint32_t voff = dd * 128 + ((((n >> 3) ^ (dd & 7))) << 4) + (n & 7) * 2;
            *(__half*)((char*)sVt + voff) = vp[e];
        }
    }
    __syncthreads();

    uint32_t sqb = smem_u32(sQ), skb = smem_u32(sK);

    {
        uint32_t a[2][4];
        #pragma unroll
        for (int kk = 0; kk < 2; kk++) {
            int ra = wid * 16 + (lane & 15);
            int kga = kk * 2 + (lane >> 4);
            ldmx4(a[kk], sqb + ra * 64 + ((kga ^ (ra & 3)) << 4));
        }
        #pragma unroll
        for (int nt = 0; nt < 4; nt++) {
            float cs[2][4] = {};
            #pragma unroll
            for (int kk = 0; kk < 2; kk++) {
                uint32_t bf[4];
                int nb = nt * 16 + (lane & 7) + ((lane >> 4) << 3);
                int kgb = kk * 2 + ((lane >> 3) & 1);
                ldmx4(bf, skb + nb * 64 + ((kgb ^ (nb & 3)) << 4));
                mma_f16(cs[0], a[kk], bf[0], bf[1]);
                mma_f16(cs[1], a[kk], bf[2], bf[3]);
            }
            int r0 = wid * 16 + (lane >> 2);
            #pragma unroll
            for (int n8 = 0; n8 < 2; n8++)
                #pragma unroll
                for (int e = 0; e < 4; e++) {
                    int row = r0 + (e >> 1) * 8;
                    int col = nt * 16 + n8 * 8 + (lane & 3) * 2 + (e & 1);
                    sS[row * SST + col] = cs[n8][e];
                }
        }
    }
    __syncthreads();

    const float scale = 0.17677669529663687f;
    const float* bb = bias + h * NTOK * NTOK;
    for (int i = wid; i < NTOK; i += 4) {
        int j1 = lane + 32;
        float v0 = (lane < NTOK) ? sS[i * SST + lane] * scale + bb[i * NTOK + lane] : -1e30f;
        float v1 = (j1 < NTOK) ? sS[i * SST + j1] * scale + bb[i * NTOK + j1] : -1e30f;
        float m = fmaxf(v0, v1);
        #pragma unroll
        for (int o = 16; o > 0; o >>= 1) m = fmaxf(m, __shfl_xor_sync(0xffffffffu, m, o));
        float e0 = (lane < NTOK) ? __expf(v0 - m) : 0.f;
        float e1 = (j1 < NTOK) ? __expf(v1 - m) : 0.f;
        float sum = e0 + e1;
        #pragma unroll
        for (int o = 16; o > 0; o >>= 1) sum += __shfl_xor_sync(0xffffffffu, sum, o);
        float inv = 1.0f / sum;
        if (lane < NTOK) {
            uint32_t poff = i * 128 + ((((lane >> 3) ^ (i & 7))) << 4) + (lane & 7) * 2;
            *(__half*)((char*)sP + poff) = __float2half_rn(e0 * inv);
        }
        if (j1 < NTOK) {
            uint32_t poff = i * 128 + ((((j1 >> 3) ^ (i & 7))) << 4) + (j1 & 7) * 2;
            *(__half*)((char*)sP + poff) = __float2half_rn(e1 * inv);
        }
    }
    __syncthreads();

    {
        uint32_t spb = smem_u32(sP), svb = smem_u32(sVt);
        float co[2][2][4] = {};
        #pragma unroll
        for (int kt = 0; kt < 4; kt++) {
            uint32_t ap[4];
            int ra = wid * 16 + (lane & 15);
            int kga = kt * 2 + (lane >> 4);
            ldmx4(ap, spb + ra * 128 + ((kga ^ (ra & 7)) << 4));
            #pragma unroll
            for (int nt = 0; nt < 2; nt++) {
                uint32_t bf[4];
                int nb = nt * 16 + (lane & 7) + ((lane >> 4) << 3);
                int kgb = kt * 2 + ((lane >> 3) & 1);
                ldmx4(bf, svb + nb * 128 + ((kgb ^ (nb & 7)) << 4));
                mma_f16(co[nt][0], ap, bf[0], bf[1]);
                mma_f16(co[nt][1], ap, bf[2], bf[3]);
            }
        }
        int r0 = wid * 16 + (lane >> 2);
        #pragma unroll
        for (int nt = 0; nt < 2; nt++)
            #pragma unroll
            for (int n8 = 0; n8 < 2; n8++)
                #pragma unroll
                for (int hf = 0; hf < 2; hf++) {
                    int row = r0 + hf * 8;
                    if (row < NTOK) {
                        int col = nt * 16 + n8 * 8 + (lane & 3) * 2;
                        __half2 hv;
                        hv.x = __float2half_rn(co[nt][n8][hf * 2]);
                        hv.y = __float2half_rn(co[nt][n8][hf * 2 + 1]);
                        *(__half2*)(out + ((size_t)b * NTOK + row) * DIM + h * HD + col) = hv;
                    }
                }
    }
}

// ---------------------------------------------------------------------------
// Launch
// ---------------------------------------------------------------------------
extern "C" void kernel_launch(void* const* d_in, const int* in_sizes, int n_in,
                              void* d_out, int out_size)
{
    const float* x          = (const float*)d_in[0];
    const float* ln1_g      = (const float*)d_in[1];
    const float* ln1_b      = (const float*)d_in[2];
    const float* qkv_w      = (const float*)d_in[3];
    const float* proj_w     = (const float*)d_in[4];
    const float* proj_b     = (const float*)d_in[5];
    const float* bias_table = (const float*)d_in[6];
    const float* ln2_g      = (const float*)d_in[7];
    const float* ln2_b      = (const float*)d_in[8];
    const float* fc1_w      = (const float*)d_in[9];
    const float* fc1_b      = (const float*)d_in[10];
    const float* fc2_w      = (const float*)d_in[11];
    const float* fc2_b      = (const float*)d_in[12];
    const int*   rel_index  = (const int*)d_in[13];
    float* out = (float*)d_out;

    __half *act, *qkvh, *hid, *wq, *wp, *w1, *w2;
    float* biasg;
    cudaGetSymbolAddress((void**)&act, g_act192);
    cudaGetSymbolAddress((void**)&qkvh, g_qkvh);
    cudaGetSymbolAddress((void**)&hid, g_hid);
    cudaGetSymbolAddress((void**)&wq, g_wqkv);
    cudaGetSymbolAddress((void**)&wp, g_wprj);
    cudaGetSymbolAddress((void**)&w1, g_wfc1);
    cudaGetSymbolAddress((void**)&w2, g_wfc2);
    cudaGetSymbolAddress((void**)&biasg, g_bias);

    cudaFuncSetAttribute(tc_gemm<576, 192, 0>, cudaFuncAttributeMaxDynamicSharedMemorySize, GEMM_SMEM);
    cudaFuncSetAttribute(tc_gemm<192, 192, 3>, cudaFuncAttributeMaxDynamicSharedMemorySize, GEMM_SMEM);
    cudaFuncSetAttribute(tc_gemm<768, 192, 2>, cudaFuncAttributeMaxDynamicSharedMemorySize, GEMM_SMEM);
    cudaFuncSetAttribute(tc_gemm<192, 768, 1>, cudaFuncAttributeMaxDynamicSharedMemorySize, GEMM_SMEM);

    // launch 1
    prep_w<<<(DIM * 576 + 255) / 256, 256>>>(qkv_w, wq, DIM, 576);
    // launch 2
    prep_misc<<<208, 256>>>(proj_w, wp, bias_table, rel_index, biasg);
    // launch 3
    ln_kernel<<<MROWS, DIM>>>(x, ln1_g, ln1_b, act);
    // launch 4
    {
        dim3 grid(3, MROWS / 128);
        tc_gemm<576, 192, 0><<<grid, 256, GEMM_SMEM>>>(act, wq, nullptr, nullptr,
                                                       nullptr, qkvh, nullptr, nullptr);
    }
    // launch 5
    attn_kernel<<<BW * HEADS, 128>>>(qkvh, biasg, act);
    // launch 6 (ncu capture target): proj + residual + fused LN2
    {
        dim3 grid(1, MROWS / 128);
        tc_gemm<192, 192, 3><<<grid, 256, GEMM_SMEM>>>(act, wp, proj_b, x,
                                                       out, act, ln2_g, ln2_b);
    }
    // launch 7
    prep_fc<<<1152, 256>>>(fc1_w, w1, fc2_w, w2);
    // launch 8
    {
        dim3 grid(4, MROWS / 128);
        tc_gemm<768, 192, 2><<<grid, 256, GEMM_SMEM>>>(act, w1, fc1_b, nullptr,
                                                       nullptr, hid, nullptr, nullptr);
    }
    // launch 9
    {
        dim3 grid(1, MROWS / 128);
        tc_gemm<192, 768, 1><<<grid, 256, GEMM_SMEM>>>(hid, w2, fc2_b, out,
                                                       out, nullptr, nullptr, nullptr);
    }
}

// round 10
// speedup vs baseline: 1.4210x; 1.4210x over previous
#include <cuda_runtime.h>
#include <cuda_fp16.h>
#include <math.h>
#include <stdint.h>

#define BW    4096
#define NTOK  49
#define DIM   192
#define HEADS 6
#define HD    32
#define HIDDEN 768
#define MROWS (BW * NTOK)   // 200704

// ---------------------------------------------------------------------------
// Scratch (allocation-free, __device__ globals)
// ---------------------------------------------------------------------------
__device__ __half g_act192[(size_t)MROWS * DIM];
__device__ __half g_qkvh[(size_t)MROWS * 3 * DIM];
__device__ __half g_hid[(size_t)MROWS * HIDDEN];

__device__ __half g_wqkv[3 * DIM * DIM];
__device__ __half g_wprj[DIM * DIM];
__device__ __half g_wfc1[DIM * HIDDEN];
__device__ __half g_wfc2[HIDDEN * DIM];
__device__ float  g_bias[HEADS * NTOK * NTOK];

// ---------------------------------------------------------------------------
// helpers
// ---------------------------------------------------------------------------
__device__ __forceinline__ uint32_t smem_u32(const void* p) {
    uint32_t a;
    asm("{ .reg .u64 t; cvta.to.shared.u64 t, %1; cvt.u32.u64 %0, t; }" : "=r"(a) : "l"(p));
    return a;
}
__device__ __forceinline__ void cpa16(uint32_t dst, const void* src) {
    asm volatile("cp.async.cg.shared.global [%0], [%1], 16;" :: "r"(dst), "l"(src));
}
__device__ __forceinline__ void cp_commit() {
    asm volatile("cp.async.commit_group;" ::: "memory");
}
__device__ __forceinline__ void cp_wait1() {
    asm volatile("cp.async.wait_group 1;" ::: "memory");
}
__device__ __forceinline__ void ldmx4(uint32_t* r, uint32_t addr) {
    asm volatile("ldmatrix.sync.aligned.m8n8.x4.shared.b16 {%0,%1,%2,%3}, [%4];"
                 : "=r"(r[0]), "=r"(r[1]), "=r"(r[2]), "=r"(r[3]) : "r"(addr));
}
__device__ __forceinline__ void mma_f16(float* c, const uint32_t* a,
                                        uint32_t b0, uint32_t b1) {
    asm volatile(
        "mma.sync.aligned.m16n8k16.row.col.f32.f16.f16.f32 "
        "{%0,%1,%2,%3}, {%4,%5,%6,%7}, {%8,%9}, {%0,%1,%2,%3};"
        : "+f"(c[0]), "+f"(c[1]), "+f"(c[2]), "+f"(c[3])
        : "r"(a[0]), "r"(a[1]), "r"(a[2]), "r"(a[3]), "r"(b0), "r"(b1));
}

// ---------------------------------------------------------------------------
// One merged prep kernel: all weight transposes + bias gather
// ---------------------------------------------------------------------------
#define PQ  (DIM * 576)              // 110592
#define PP  (DIM * DIM)              // 36864
#define P1  (DIM * HIDDEN)           // 147456
#define P2  (HIDDEN * DIM)           // 147456
#define PB  (HEADS * NTOK * NTOK)    // 14406
#define PTOT (PQ + PP + P1 + P2 + PB)

__global__ void prep_all(
    const float* __restrict__ Wq, __half* __restrict__ Wqt,
    const float* __restrict__ Wp, __half* __restrict__ Wpt,
    const float* __restrict__ W1, __half* __restrict__ W1t,
    const float* __restrict__ W2, __half* __restrict__ W2t,
    const float* __restrict__ table, const int* __restrict__ ridx,
    float* __restrict__ biasg)
{
    for (int idx = blockIdx.x * blockDim.x + threadIdx.x; idx < PTOT;
         idx += gridDim.x * blockDim.x) {
        if (idx < PQ) {
            int k = idx / 576, n = idx - k * 576;
            Wqt[(size_t)n * DIM + k] = __float2half_rn(Wq[idx]);
        } else if (idx < PQ + PP) {
            int i = idx - PQ;
            int k = i / DIM, n = i - k * DIM;
            Wpt[(size_t)n * DIM + k] = __float2half_rn(Wp[i]);
        } else if (idx < PQ + PP + P1) {
            int i = idx - PQ - PP;
            int k = i / HIDDEN, n = i - k * HIDDEN;
            W1t[(size_t)n * DIM + k] = __float2half_rn(W1[i]);
        } else if (idx < PQ + PP + P1 + P2) {
            int i = idx - PQ - PP - P1;
            int k = i / DIM, n = i - k * DIM;
            W2t[(size_t)n * HIDDEN + k] = __float2half_rn(W2[i]);
        } else {
            int i = idx - PQ - PP - P1 - P2;
            int h = i / (NTOK * NTOK), ij = i % (NTOK * NTOK);
            biasg[i] = table[ridx[ij] * HEADS + h];
        }
    }
}

// ---------------------------------------------------------------------------
// LayerNorm -> fp16
// ---------------------------------------------------------------------------
__global__ __launch_bounds__(DIM) void ln_kernel(
    const float* __restrict__ x, const float* __restrict__ g,
    const float* __restrict__ b, __half* __restrict__ o)
{
    int row = blockIdx.x;
    int t = threadIdx.x;
    float v = x[(size_t)row * DIM + t];
    float s = v, s2 = v * v;
    #pragma unroll
    for (int of = 16; of > 0; of >>= 1) {
        s  += __shfl_down_sync(0xffffffffu, s,  of);
        s2 += __shfl_down_sync(0xffffffffu, s2, of);
    }
    __shared__ float r0[6], r1[6];
    if ((t & 31) == 0) { r0[t >> 5] = s; r1[t >> 5] = s2; }
    __syncthreads();
    if (t == 0) {
        float a = 0.f, c = 0.f;
        #pragma unroll
        for (int i = 0; i < 6; i++) { a += r0[i]; c += r1[i]; }
        r0[0] = a * (1.0f / DIM); r1[0] = c * (1.0f / DIM);
    }
    __syncthreads();
    float mu = r0[0];
    float var = r1[0] - mu * mu;
    float y = (v - mu) * rsqrtf(var + 1e-5f) * g[t] + b[t];
    o[(size_t)row * DIM + t] = __float2half_rn(y);
}

// ---------------------------------------------------------------------------
// fp16 HMMA GEMM (R8 config): block 128x192, 512 threads, 16 warps (4x4),
// warp tile 32x48, K-step 32, 3-stage cp.async, loads issued BEFORE compute.
// EPI: 0 -> fp16 | 1 bias+res -> fp32 | 2 bias+gelu -> fp16
//      3 bias+res -> fp32 + fused LN -> fp16 (N_TOTAL==192)
// ---------------------------------------------------------------------------
#define STAGE   20480u  // A 8K + B 12K
#define O_B     8192u
#define GEMM_SMEM (3 * 20480)

template <int N_TOTAL, int K_TOTAL, int EPI>
__global__ __launch_bounds__(512, 1) void tc_gemm(
    const __half* __restrict__ A, const __half* __restrict__ B,
    const float* __restrict__ bias, const float* __restrict__ res,
    float* __restrict__ Cf, __half* __restrict__ Ch,
    const float* __restrict__ lng, const float* __restrict__ lnb)
{
    constexpr int KSTEPS = K_TOTAL / 32;

    extern __shared__ char smem[];
    __shared__ float s_red[128 * 8];
    uint32_t sb = smem_u32(smem);
    int tid = threadIdx.x, lane = tid & 31, wid = tid >> 5;
    int wm = wid & 3, wn = wid >> 2;          // 4 x 4 warp grid
    size_t rowbase = (size_t)blockIdx.y * 128;
    int colbase = blockIdx.x * 192;

    auto load_stage = [&](int s) {
        uint32_t base = sb + (uint32_t)(s % 3) * STAGE;
        {
            int r = tid >> 2, kg = tid & 3;
            uint32_t soff = r * 64 + ((kg ^ (r & 3)) << 4);
            cpa16(base + soff, A + (rowbase + r) * K_TOTAL + s * 32 + kg * 8);
        }
        #pragma unroll
        for (int i = tid; i < 768; i += 512) {
            int r = i >> 2, kg = i & 3;
            uint32_t soff = r * 64 + ((kg ^ (r & 3)) << 4);
            cpa16(base + O_B + soff, B + (size_t)(colbase + r) * K_TOTAL + s * 32 + kg * 8);
        }
    };

    uint32_t aoff[2][2], boff[3][2];
    #pragma unroll
    for (int mt = 0; mt < 2; mt++)
        #pragma unroll
        for (int kk = 0; kk < 2; kk++) {
            int ra = wm * 32 + mt * 16 + (lane & 15);
            int kga = kk * 2 + (lane >> 4);
            aoff[mt][kk] = ra * 64 + ((kga ^ (ra & 3)) << 4);
        }
    #pragma unroll
    for (int np = 0; np < 3; np++)
        #pragma unroll
        for (int kk = 0; kk < 2; kk++) {
            int nb = wn * 48 + np * 16 + (lane & 7) + ((lane >> 4) << 3);
            int kgb = kk * 2 + ((lane >> 3) & 1);
            boff[np][kk] = nb * 64 + ((kgb ^ (nb & 3)) << 4);
        }

    float acc[2][6][4] = {};

    load_stage(0); cp_commit();
    load_stage(1); cp_commit();

    for (int s = 0; s < KSTEPS; s++) {
        cp_wait1();
        __syncthreads();
        // issue next stage's loads BEFORE compute (buffer (s+2)%3 is free)
        if (s + 2 < KSTEPS) load_stage(s + 2);
        cp_commit();
        uint32_t base = sb + (uint32_t)(s % 3) * STAGE;
        #pragma unroll
        for (int kk = 0; kk < 2; kk++) {
            uint32_t ah[2][4];
            ldmx4(ah[0], base + aoff[0][kk]);
            ldmx4(ah[1], base + aoff[1][kk]);
            #pragma unroll
            for (int np = 0; np < 3; np++) {
                uint32_t bf[4];
                ldmx4(bf, base + O_B + boff[np][kk]);
                #pragma unroll
                for (int mt = 0; mt < 2; mt++) {
                    mma_f16(acc[mt][np * 2],     ah[mt], bf[0], bf[1]);
                    mma_f16(acc[mt][np * 2 + 1], ah[mt], bf[2], bf[3]);
                }
            }
        }
    }

    // ---- epilogue ----
    if (EPI == 3) {
        float psum[2][2] = {}, psq[2][2] = {};
        #pragma unroll
        for (int mt = 0; mt < 2; mt++)
            #pragma unroll
            for (int nt = 0; nt < 6; nt++) {
                int c = colbase + wn * 48 + nt * 8 + (lane & 3) * 2;
                #pragma unroll
                for (int half = 0; half < 2; half++) {
                    size_t row = rowbase + wm * 32 + mt * 16 + (lane >> 2) + half * 8;
                    float v0 = acc[mt][nt][half * 2]     + bias[c];
                    float v1 = acc[mt][nt][half * 2 + 1] + bias[c + 1];
                    const float2 rv = *(const float2*)(res + row * N_TOTAL + c);
                    v0 += rv.x; v1 += rv.y;
                    acc[mt][nt][half * 2] = v0;
                    acc[mt][nt][half * 2 + 1] = v1;
                    psum[mt][half] += v0 + v1;
                    psq[mt][half]  += v0 * v0 + v1 * v1;
                }
            }
        #pragma unroll
        for (int o = 1; o <= 2; o <<= 1)
            #pragma unroll
            for (int mt = 0; mt < 2; mt++)
                #pragma unroll
                for (int half = 0; half < 2; half++) {
                    psum[mt][half] += __shfl_xor_sync(0xffffffffu, psum[mt][half], o);
                    psq[mt][half]  += __shfl_xor_sync(0xffffffffu, psq[mt][half],  o);
                }
        if ((lane & 3) == 0) {
            #pragma unroll
            for (int mt = 0; mt < 2; mt++)
                #pragma unroll
                for (int half = 0; half < 2; half++) {
                    int lrow = wm * 32 + mt * 16 + (lane >> 2) + half * 8;
                    s_red[lrow * 8 + wn * 2]     = psum[mt][half];
                    s_red[lrow * 8 + wn * 2 + 1] = psq[mt][half];
                }
        }
        __syncthreads();
        float mu[2][2], rs[2][2];
        #pragma unroll
        for (int mt = 0; mt < 2; mt++)
            #pragma unroll
            for (int half = 0; half < 2; half++) {
                int lrow = wm * 32 + mt * 16 + (lane >> 2) + half * 8;
                float S = 0.f, Q = 0.f;
                #pragma unroll
                for (int w = 0; w < 4; w++) {
                    S += s_red[lrow * 8 + w * 2];
                    Q += s_red[lrow * 8 + w * 2 + 1];
                }
                float m = S * (1.0f / N_TOTAL);
                float var = Q * (1.0f / N_TOTAL) - m * m;
                mu[mt][half] = m;
                rs[mt][half] = rsqrtf(var + 1e-5f);
            }
        #pragma unroll
        for (int mt = 0; mt < 2; mt++)
            #pragma unroll
            for (int nt = 0; nt < 6; nt++) {
                int c = colbase + wn * 48 + nt * 8 + (lane & 3) * 2;
                float g0 = lng[c], g1 = lng[c + 1];
                float b0 = lnb[c], b1 = lnb[c + 1];
                #pragma unroll
                for (int half = 0; half < 2; half++) {
                    size_t row = rowbase + wm * 32 + mt * 16 + (lane >> 2) + half * 8;
                    float v0 = acc[mt][nt][half * 2];
                    float v1 = acc[mt][nt][half * 2 + 1];
                    float2 ov; ov.x = v0; ov.y = v1;
                    *(float2*)(Cf + row * N_TOTAL + c) = ov;
                    float n0 = (v0 - mu[mt][half]) * rs[mt][half] * g0 + b0;
                    float n1 = (v1 - mu[mt][half]) * rs[mt][half] * g1 + b1;
                    __half2 hv; hv.x = __float2half_rn(n0); hv.y = __float2half_rn(n1);
                    *(__half2*)(Ch + row * N_TOTAL + c) = hv;
                }
            }
    } else {
        #pragma unroll
        for (int mt = 0; mt < 2; mt++) {
            size_t rbase = rowbase + wm * 32 + mt * 16 + (lane >> 2);
            #pragma unroll
            for (int nt = 0; nt < 6; nt++) {
                int c = colbase + wn * 48 + nt * 8 + (lane & 3) * 2;
                #pragma unroll
                for (int half = 0; half < 2; half++) {
                    size_t row = rbase + half * 8;
                    float v0 = acc[mt][nt][half * 2];
                    float v1 = acc[mt][nt][half * 2 + 1];
                    if (EPI >= 1) { v0 += bias[c]; v1 += bias[c + 1]; }
                    if (EPI == 2) {
                        v0 = 0.5f * v0 * (1.0f + erff(v0 * 0.70710678118654752f));
                        v1 = 0.5f * v1 * (1.0f + erff(v1 * 0.70710678118654752f));
                    }
                    if (EPI == 1) {
                        const float2 rv = *(const float2*)(res + row * N_TOTAL + c);
                        float2 ov; ov.x = v0 + rv.x; ov.y = v1 + rv.y;
                        *(float2*)(Cf + row * N_TOTAL + c) = ov;
                    } else {
                        __half2 hv; hv.x = __float2half_rn(v0); hv.y = __float2half_rn(v1);
                        *(__half2*)(Ch + row * N_TOTAL + c) = hv;
                    }
                }
            }
        }
    }
}

// ---------------------------------------------------------------------------
// Tensor-core window attention
// ---------------------------------------------------------------------------
__global__ __launch_bounds__(128) void attn_kernel(
    const __half* __restrict__ qkv, const float* __restrict__ bias,
    __half* __restrict__ out)
{
    int b = blockIdx.x / HEADS;
    int h = blockIdx.x % HEADS;
    int tid = threadIdx.x, lane = tid & 31, wid = tid >> 5;

    __shared__ __half sQ[64 * 32], sK[64 * 32], sVt[32 * 64], sP[64 * 64];
    __shared__ float sS[64 * 65];

    for (int i = tid; i < 256; i += 128) {
        ((uint4*)sQ)[i]  = make_uint4(0, 0, 0, 0);
        ((uint4*)sK)[i]  = make_uint4(0, 0, 0, 0);
        ((uint4*)sVt)[i] = make_uint4(0, 0, 0, 0);
    }
    for (int i = tid; i < 512; i += 128) ((uint4*)sP)[i] = make_uint4(0, 0, 0, 0);
    __syncthreads();

    const __half* base = qkv + (size_t)b * NTOK * (3 * DIM);
    for (int idx = tid; idx < NTOK * HD / 4; idx += 128) {
        int n = idx >> 3, dc = idx & 7;
        int d = dc * 4;
        const __half* tp = base + n * (3 * DIM) + h * HD + d;
        uint2 qv = *(const uint2*)tp;
        uint2 kv = *(const uint2*)(tp + DIM);
        uint2 vv = *(const uint2*)(tp + 2 * DIM);
        uint32_t qoff = n * 64 + ((((d >> 3) ^ (n & 3))) << 4) + (d & 7) * 2;
        *(uint2*)((char*)sQ + qoff) = qv;
        *(uint2*)((char*)sK + qoff) = kv;
        const __half* vp = (const __half*)&vv;
        #pragma unroll
        for (int e = 0; e < 4; e++) {
            int dd = d + e;
            uint32_t voff = dd * 128 + ((((n >> 3) ^ (dd & 7))) << 4) + (n & 7) * 2;
            *(__half*)((char*)sVt + voff) = vp[e];
        }
    }
    __syncthreads();

    uint32_t sqb = smem_u32(sQ), skb = smem_u32(sK);

    {
        uint32_t a[2][4];
        #pragma unroll
        for (int kk = 0; kk < 2; kk++) {
            int ra = wid * 16 + (lane & 15);
            int kga = kk * 2 + (lane >> 4);
            ldmx4(a[kk], sqb + ra * 64 + ((kga ^ (ra & 3)) << 4));
        }
        #pragma unroll
        for (int nt = 0; nt < 4; nt++) {
            float cs[2][4] = {};
            #pragma unroll
            for (int kk = 0; kk < 2; kk++) {
                uint32_t bf[4];
                int nb = nt * 16 + (lane & 7) + ((lane >> 4) << 3);
                int kgb = kk * 2 + ((lane >> 3) & 1);
                ldmx4(bf, skb + nb * 64 + ((kgb ^ (nb & 3)) << 4));
                mma_f16(cs[0], a[kk], bf[0], bf[1]);
                mma_f16(cs[1], a[kk], bf[2], bf[3]);
            }
            int r0 = wid * 16 + (lane >> 2);
            #pragma unroll
            for (int n8 = 0; n8 < 2; n8++)
                #pragma unroll
                for (int e = 0; e < 4; e++) {
                    int row = r0 + (e >> 1) * 8;
                    int col = nt * 16 + n8 * 8 + (lane & 3) * 2 + (e & 1);
                    sS[row * 65 + col] = cs[n8][e];
                }
        }
    }
    __syncthreads();

    const float scale = 0.17677669529663687f;
    const float* bb = bias + h * NTOK * NTOK;
    for (int i = wid; i < NTOK; i += 4) {
        int j1 = lane + 32;
        float v0 = (lane < NTOK) ? sS[i * 65 + lane] * scale + bb[i * NTOK + lane] : -1e30f;
        float v1 = (j1 < NTOK) ? sS[i * 65 + j1] * scale + bb[i * NTOK + j1] : -1e30f;
        float m = fmaxf(v0, v1);
        #pragma unroll
        for (int o = 16; o > 0; o >>= 1) m = fmaxf(m, __shfl_xor_sync(0xffffffffu, m, o));
        float e0 = (lane < NTOK) ? __expf(v0 - m) : 0.f;
        float e1 = (j1 < NTOK) ? __expf(v1 - m) : 0.f;
        float sum = e0 + e1;
        #pragma unroll
        for (int o = 16; o > 0; o >>= 1) sum += __shfl_xor_sync(0xffffffffu, sum, o);
        float inv = 1.0f / sum;
        if (lane < NTOK) {
            uint32_t poff = i * 128 + ((((lane >> 3) ^ (i & 7))) << 4) + (lane & 7) * 2;
            *(__half*)((char*)sP + poff) = __float2half_rn(e0 * inv);
        }
        if (j1 < NTOK) {
            uint32_t poff = i * 128 + ((((j1 >> 3) ^ (i & 7))) << 4) + (j1 & 7) * 2;
            *(__half*)((char*)sP + poff) = __float2half_rn(e1 * inv);
        }
    }
    __syncthreads();

    {
        uint32_t spb = smem_u32(sP), svb = smem_u32(sVt);
        float co[2][2][4] = {};
        #pragma unroll
        for (int kt = 0; kt < 4; kt++) {
            uint32_t ap[4];
            int ra = wid * 16 + (lane & 15);
            int kga = kt * 2 + (lane >> 4);
            ldmx4(ap, spb + ra * 128 + ((kga ^ (ra & 7)) << 4));
            #pragma unroll
            for (int nt = 0; nt < 2; nt++) {
                uint32_t bf[4];
                int nb = nt * 16 + (lane & 7) + ((lane >> 4) << 3);
                int kgb = kt * 2 + ((lane >> 3) & 1);
                ldmx4(bf, svb + nb * 128 + ((kgb ^ (nb & 7)) << 4));
                mma_f16(co[nt][0], ap, bf[0], bf[1]);
                mma_f16(co[nt][1], ap, bf[2], bf[3]);
            }
        }
        int r0 = wid * 16 + (lane >> 2);
        #pragma unroll
        for (int nt = 0; nt < 2; nt++)
            #pragma unroll
            for (int n8 = 0; n8 < 2; n8++)
                #pragma unroll
                for (int hf = 0; hf < 2; hf++) {
                    int row = r0 + hf * 8;
                    if (row < NTOK) {
                        int col = nt * 16 + n8 * 8 + (lane & 3) * 2;
                        __half2 hv;
                        hv.x = __float2half_rn(co[nt][n8][hf * 2]);
                        hv.y = __float2half_rn(co[nt][n8][hf * 2 + 1]);
                        *(__half2*)(out + ((size_t)b * NTOK + row) * DIM + h * HD + col) = hv;
                    }
                }
    }
}

// ---------------------------------------------------------------------------
// Launch (7 launches; #6 = fc1 GEMM = ncu capture target)
// ---------------------------------------------------------------------------
extern "C" void kernel_launch(void* const* d_in, const int* in_sizes, int n_in,
                              void* d_out, int out_size)
{
    const float* x          = (const float*)d_in[0];
    const float* ln1_g      = (const float*)d_in[1];
    const float* ln1_b      = (const float*)d_in[2];
    const float* qkv_w      = (const float*)d_in[3];
    const float* proj_w     = (const float*)d_in[4];
    const float* proj_b     = (const float*)d_in[5];
    const float* bias_table = (const float*)d_in[6];
    const float* ln2_g      = (const float*)d_in[7];
    const float* ln2_b      = (const float*)d_in[8];
    const float* fc1_w      = (const float*)d_in[9];
    const float* fc1_b      = (const float*)d_in[10];
    const float* fc2_w      = (const float*)d_in[11];
    const float* fc2_b      = (const float*)d_in[12];
    const int*   rel_index  = (const int*)d_in[13];
    float* out = (float*)d_out;

    __half *act, *qkvh, *hid, *wq, *wp, *w1, *w2;
    float* biasg;
    cudaGetSymbolAddress((void**)&act, g_act192);
    cudaGetSymbolAddress((void**)&qkvh, g_qkvh);
    cudaGetSymbolAddress((void**)&hid, g_hid);
    cudaGetSymbolAddress((void**)&wq, g_wqkv);
    cudaGetSymbolAddress((void**)&wp, g_wprj);
    cudaGetSymbolAddress((void**)&w1, g_wfc1);
    cudaGetSymbolAddress((void**)&w2, g_wfc2);
    cudaGetSymbolAddress((void**)&biasg, g_bias);

    cudaFuncSetAttribute(tc_gemm<576, 192, 0>, cudaFuncAttributeMaxDynamicSharedMemorySize, GEMM_SMEM);
    cudaFuncSetAttribute(tc_gemm<192, 192, 3>, cudaFuncAttributeMaxDynamicSharedMemorySize, GEMM_SMEM);
    cudaFuncSetAttribute(tc_gemm<768, 192, 2>, cudaFuncAttributeMaxDynamicSharedMemorySize, GEMM_SMEM);
    cudaFuncSetAttribute(tc_gemm<192, 768, 1>, cudaFuncAttributeMaxDynamicSharedMemorySize, GEMM_SMEM);

    // launch 1: all prep
    prep_all<<<894, 512>>>(qkv_w, wq, proj_w, wp, fc1_w, w1, fc2_w, w2,
                           bias_table, rel_index, biasg);
    // launch 2: LN1
    ln_kernel<<<MROWS, DIM>>>(x, ln1_g, ln1_b, act);
    // launch 3: qkv GEMM
    {
        dim3 grid(3, MROWS / 128);
        tc_gemm<576, 192, 0><<<grid, 512, GEMM_SMEM>>>(act, wq, nullptr, nullptr,
                                                       nullptr, qkvh, nullptr, nullptr);
    }
    // launch 4: attention
    attn_kernel<<<BW * HEADS, 128>>>(qkvh, biasg, act);
    // launch 5: proj + residual + fused LN2
    {
        dim3 grid(1, MROWS / 128);
        tc_gemm<192, 192, 3><<<grid, 512, GEMM_SMEM>>>(act, wp, proj_b, x,
                                                       out, act, ln2_g, ln2_b);
    }
    // launch 6 (ncu capture): fc1 + GELU
    {
        dim3 grid(4, MROWS / 128);
        tc_gemm<768, 192, 2><<<grid, 512, GEMM_SMEM>>>(act, w1, fc1_b, nullptr,
                                                       nullptr, hid, nullptr, nullptr);
    }
    // launch 7: fc2 + residual
    {
        dim3 grid(1, MROWS / 128);
        tc_gemm<192, 768, 1><<<grid, 512, GEMM_SMEM>>>(hid, w2, fc2_b, out,
                                                       out, nullptr, nullptr, nullptr);
    }
}

// round 12
// speedup vs baseline: 1.5453x; 1.0874x over previous
#include <cuda_runtime.h>
#include <cuda_fp16.h>
#include <math.h>
#include <stdint.h>

#define BW    4096
#define NTOK  49
#define DIM   192
#define HEADS 6
#define HD    32
#define HIDDEN 768
#define MROWS (BW * NTOK)   // 200704

// ---------------------------------------------------------------------------
// Scratch (allocation-free, __device__ globals)
// ---------------------------------------------------------------------------
__device__ __half g_act192[(size_t)MROWS * DIM];
__device__ __half g_qkvh[(size_t)MROWS * 3 * DIM];
__device__ __half g_hid[(size_t)MROWS * HIDDEN];

__device__ __half g_wqkv[3 * DIM * DIM];
__device__ __half g_wprj[DIM * DIM];
__device__ __half g_wfc1[DIM * HIDDEN];
__device__ __half g_wfc2[HIDDEN * DIM];
__device__ float  g_bias[HEADS * NTOK * NTOK];

// ---------------------------------------------------------------------------
// helpers
// ---------------------------------------------------------------------------
__device__ __forceinline__ uint32_t smem_u32(const void* p) {
    uint32_t a;
    asm("{ .reg .u64 t; cvta.to.shared.u64 t, %1; cvt.u32.u64 %0, t; }" : "=r"(a) : "l"(p));
    return a;
}
__device__ __forceinline__ void cpa16(uint32_t dst, const void* src) {
    asm volatile("cp.async.cg.shared.global [%0], [%1], 16;" :: "r"(dst), "l"(src));
}
__device__ __forceinline__ void cp_commit() {
    asm volatile("cp.async.commit_group;" ::: "memory");
}
__device__ __forceinline__ void cp_wait1() {
    asm volatile("cp.async.wait_group 1;" ::: "memory");
}
__device__ __forceinline__ void ldmx4(uint32_t* r, uint32_t addr) {
    asm volatile("ldmatrix.sync.aligned.m8n8.x4.shared.b16 {%0,%1,%2,%3}, [%4];"
                 : "=r"(r[0]), "=r"(r[1]), "=r"(r[2]), "=r"(r[3]) : "r"(addr));
}
__device__ __forceinline__ void mma_f16(float* c, const uint32_t* a,
                                        uint32_t b0, uint32_t b1) {
    asm volatile(
        "mma.sync.aligned.m16n8k16.row.col.f32.f16.f16.f32 "
        "{%0,%1,%2,%3}, {%4,%5,%6,%7}, {%8,%9}, {%0,%1,%2,%3};"
        : "+f"(c[0]), "+f"(c[1]), "+f"(c[2]), "+f"(c[3])
        : "r"(a[0]), "r"(a[1]), "r"(a[2]), "r"(a[3]), "r"(b0), "r"(b1));
}

// ---------------------------------------------------------------------------
// One merged prep kernel: all weight transposes + bias gather
// ---------------------------------------------------------------------------
#define PQ  (DIM * 576)
#define PP  (DIM * DIM)
#define P1  (DIM * HIDDEN)
#define P2  (HIDDEN * DIM)
#define PB  (HEADS * NTOK * NTOK)
#define PTOT (PQ + PP + P1 + P2 + PB)

__global__ void prep_all(
    const float* __restrict__ Wq, __half* __restrict__ Wqt,
    const float* __restrict__ Wp, __half* __restrict__ Wpt,
    const float* __restrict__ W1, __half* __restrict__ W1t,
    const float* __restrict__ W2, __half* __restrict__ W2t,
    const float* __restrict__ table, const int* __restrict__ ridx,
    float* __restrict__ biasg)
{
    for (int idx = blockIdx.x * blockDim.x + threadIdx.x; idx < PTOT;
         idx += gridDim.x * blockDim.x) {
        if (idx < PQ) {
            int k = idx / 576, n = idx - k * 576;
            Wqt[(size_t)n * DIM + k] = __float2half_rn(Wq[idx]);
        } else if (idx < PQ + PP) {
            int i = idx - PQ;
            int k = i / DIM, n = i - k * DIM;
            Wpt[(size_t)n * DIM + k] = __float2half_rn(Wp[i]);
        } else if (idx < PQ + PP + P1) {
            int i = idx - PQ - PP;
            int k = i / HIDDEN, n = i - k * HIDDEN;
            W1t[(size_t)n * DIM + k] = __float2half_rn(W1[i]);
        } else if (idx < PQ + PP + P1 + P2) {
            int i = idx - PQ - PP - P1;
            int k = i / DIM, n = i - k * DIM;
            W2t[(size_t)n * HIDDEN + k] = __float2half_rn(W2[i]);
        } else {
            int i = idx - PQ - PP - P1 - P2;
            int h = i / (NTOK * NTOK), ij = i % (NTOK * NTOK);
            biasg[i] = table[ridx[ij] * HEADS + h];
        }
    }
}

// ---------------------------------------------------------------------------
// LayerNorm -> fp16
// ---------------------------------------------------------------------------
__global__ __launch_bounds__(DIM) void ln_kernel(
    const float* __restrict__ x, const float* __restrict__ g,
    const float* __restrict__ b, __half* __restrict__ o)
{
    int row = blockIdx.x;
    int t = threadIdx.x;
    float v = x[(size_t)row * DIM + t];
    float s = v, s2 = v * v;
    #pragma unroll
    for (int of = 16; of > 0; of >>= 1) {
        s  += __shfl_down_sync(0xffffffffu, s,  of);
        s2 += __shfl_down_sync(0xffffffffu, s2, of);
    }
    __shared__ float r0[6], r1[6];
    if ((t & 31) == 0) { r0[t >> 5] = s; r1[t >> 5] = s2; }
    __syncthreads();
    if (t == 0) {
        float a = 0.f, c = 0.f;
        #pragma unroll
        for (int i = 0; i < 6; i++) { a += r0[i]; c += r1[i]; }
        r0[0] = a * (1.0f / DIM); r1[0] = c * (1.0f / DIM);
    }
    __syncthreads();
    float mu = r0[0];
    float var = r1[0] - mu * mu;
    float y = (v - mu) * rsqrtf(var + 1e-5f) * g[t] + b[t];
    o[(size_t)row * DIM + t] = __float2half_rn(y);
}

// ---------------------------------------------------------------------------
// fp16 HMMA GEMM (unchanged R10 config)
// ---------------------------------------------------------------------------
#define STAGE   20480u
#define O_B     8192u
#define GEMM_SMEM (3 * 20480)

template <int N_TOTAL, int K_TOTAL, int EPI>
__global__ __launch_bounds__(512, 1) void tc_gemm(
    const __half* __restrict__ A, const __half* __restrict__ B,
    const float* __restrict__ bias, const float* __restrict__ res,
    float* __restrict__ Cf, __half* __restrict__ Ch,
    const float* __restrict__ lng, const float* __restrict__ lnb)
{
    constexpr int KSTEPS = K_TOTAL / 32;

    extern __shared__ char smem[];
    __shared__ float s_red[128 * 8];
    uint32_t sb = smem_u32(smem);
    int tid = threadIdx.x, lane = tid & 31, wid = tid >> 5;
    int wm = wid & 3, wn = wid >> 2;
    size_t rowbase = (size_t)blockIdx.y * 128;
    int colbase = blockIdx.x * 192;

    auto load_stage = [&](int s) {
        uint32_t base = sb + (uint32_t)(s % 3) * STAGE;
        {
            int r = tid >> 2, kg = tid & 3;
            uint32_t soff = r * 64 + ((kg ^ (r & 3)) << 4);
            cpa16(base + soff, A + (rowbase + r) * K_TOTAL + s * 32 + kg * 8);
        }
        #pragma unroll
        for (int i = tid; i < 768; i += 512) {
            int r = i >> 2, kg = i & 3;
            uint32_t soff = r * 64 + ((kg ^ (r & 3)) << 4);
            cpa16(base + O_B + soff, B + (size_t)(colbase + r) * K_TOTAL + s * 32 + kg * 8);
        }
    };

    uint32_t aoff[2][2], boff[3][2];
    #pragma unroll
    for (int mt = 0; mt < 2; mt++)
        #pragma unroll
        for (int kk = 0; kk < 2; kk++) {
            int ra = wm * 32 + mt * 16 + (lane & 15);
            int kga = kk * 2 + (lane >> 4);
            aoff[mt][kk] = ra * 64 + ((kga ^ (ra & 3)) << 4);
        }
    #pragma unroll
    for (int np = 0; np < 3; np++)
        #pragma unroll
        for (int kk = 0; kk < 2; kk++) {
            int nb = wn * 48 + np * 16 + (lane & 7) + ((lane >> 4) << 3);
            int kgb = kk * 2 + ((lane >> 3) & 1);
            boff[np][kk] = nb * 64 + ((kgb ^ (nb & 3)) << 4);
        }

    float acc[2][6][4] = {};

    load_stage(0); cp_commit();
    load_stage(1); cp_commit();

    for (int s = 0; s < KSTEPS; s++) {
        cp_wait1();
        __syncthreads();
        if (s + 2 < KSTEPS) load_stage(s + 2);
        cp_commit();
        uint32_t base = sb + (uint32_t)(s % 3) * STAGE;
        #pragma unroll
        for (int kk = 0; kk < 2; kk++) {
            uint32_t ah[2][4];
            ldmx4(ah[0], base + aoff[0][kk]);
            ldmx4(ah[1], base + aoff[1][kk]);
            #pragma unroll
            for (int np = 0; np < 3; np++) {
                uint32_t bf[4];
                ldmx4(bf, base + O_B + boff[np][kk]);
                #pragma unroll
                for (int mt = 0; mt < 2; mt++) {
                    mma_f16(acc[mt][np * 2],     ah[mt], bf[0], bf[1]);
                    mma_f16(acc[mt][np * 2 + 1], ah[mt], bf[2], bf[3]);
                }
            }
        }
    }

    if (EPI == 3) {
        float psum[2][2] = {}, psq[2][2] = {};
        #pragma unroll
        for (int mt = 0; mt < 2; mt++)
            #pragma unroll
            for (int nt = 0; nt < 6; nt++) {
                int c = colbase + wn * 48 + nt * 8 + (lane & 3) * 2;
                #pragma unroll
                for (int half = 0; half < 2; half++) {
                    size_t row = rowbase + wm * 32 + mt * 16 + (lane >> 2) + half * 8;
                    float v0 = acc[mt][nt][half * 2]     + bias[c];
                    float v1 = acc[mt][nt][half * 2 + 1] + bias[c + 1];
                    const float2 rv = *(const float2*)(res + row * N_TOTAL + c);
                    v0 += rv.x; v1 += rv.y;
                    acc[mt][nt][half * 2] = v0;
                    acc[mt][nt][half * 2 + 1] = v1;
                    psum[mt][half] += v0 + v1;
                    psq[mt][half]  += v0 * v0 + v1 * v1;
                }
            }
        #pragma unroll
        for (int o = 1; o <= 2; o <<= 1)
            #pragma unroll
            for (int mt = 0; mt < 2; mt++)
                #pragma unroll
                for (int half = 0; half < 2; half++) {
                    psum[mt][half] += __shfl_xor_sync(0xffffffffu, psum[mt][half], o);
                    psq[mt][half]  += __shfl_xor_sync(0xffffffffu, psq[mt][half],  o);
                }
        if ((lane & 3) == 0) {
            #pragma unroll
            for (int mt = 0; mt < 2; mt++)
                #pragma unroll
                for (int half = 0; half < 2; half++) {
                    int lrow = wm * 32 + mt * 16 + (lane >> 2) + half * 8;
                    s_red[lrow * 8 + wn * 2]     = psum[mt][half];
                    s_red[lrow * 8 + wn * 2 + 1] = psq[mt][half];
                }
        }
        __syncthreads();
        float mu[2][2], rs[2][2];
        #pragma unroll
        for (int mt = 0; mt < 2; mt++)
            #pragma unroll
            for (int half = 0; half < 2; half++) {
                int lrow = wm * 32 + mt * 16 + (lane >> 2) + half * 8;
                float S = 0.f, Q = 0.f;
                #pragma unroll
                for (int w = 0; w < 4; w++) {
                    S += s_red[lrow * 8 + w * 2];
                    Q += s_red[lrow * 8 + w * 2 + 1];
                }
                float m = S * (1.0f / N_TOTAL);
                float var = Q * (1.0f / N_TOTAL) - m * m;
                mu[mt][half] = m;
                rs[mt][half] = rsqrtf(var + 1e-5f);
            }
        #pragma unroll
        for (int mt = 0; mt < 2; mt++)
            #pragma unroll
            for (int nt = 0; nt < 6; nt++) {
                int c = colbase + wn * 48 + nt * 8 + (lane & 3) * 2;
                float g0 = lng[c], g1 = lng[c + 1];
                float b0 = lnb[c], b1 = lnb[c + 1];
                #pragma unroll
                for (int half = 0; half < 2; half++) {
                    size_t row = rowbase + wm * 32 + mt * 16 + (lane >> 2) + half * 8;
                    float v0 = acc[mt][nt][half * 2];
                    float v1 = acc[mt][nt][half * 2 + 1];
                    float2 ov; ov.x = v0; ov.y = v1;
                    *(float2*)(Cf + row * N_TOTAL + c) = ov;
                    float n0 = (v0 - mu[mt][half]) * rs[mt][half] * g0 + b0;
                    float n1 = (v1 - mu[mt][half]) * rs[mt][half] * g1 + b1;
                    __half2 hv; hv.x = __float2half_rn(n0); hv.y = __float2half_rn(n1);
                    *(__half2*)(Ch + row * N_TOTAL + c) = hv;
                }
            }
    } else {
        #pragma unroll
        for (int mt = 0; mt < 2; mt++) {
            size_t rbase = rowbase + wm * 32 + mt * 16 + (lane >> 2);
            #pragma unroll
            for (int nt = 0; nt < 6; nt++) {
                int c = colbase + wn * 48 + nt * 8 + (lane & 3) * 2;
                #pragma unroll
                for (int half = 0; half < 2; half++) {
                    size_t row = rbase + half * 8;
                    float v0 = acc[mt][nt][half * 2];
                    float v1 = acc[mt][nt][half * 2 + 1];
                    if (EPI >= 1) { v0 += bias[c]; v1 += bias[c + 1]; }
                    if (EPI == 2) {
                        v0 = 0.5f * v0 * (1.0f + erff(v0 * 0.70710678118654752f));
                        v1 = 0.5f * v1 * (1.0f + erff(v1 * 0.70710678118654752f));
                    }
                    if (EPI == 1) {
                        const float2 rv = *(const float2*)(res + row * N_TOTAL + c);
                        float2 ov; ov.x = v0 + rv.x; ov.y = v1 + rv.y;
                        *(float2*)(Cf + row * N_TOTAL + c) = ov;
                    } else {
                        __half2 hv; hv.x = __float2half_rn(v0); hv.y = __float2half_rn(v1);
                        *(__half2*)(Ch + row * N_TOTAL + c) = hv;
                    }
                }
            }
        }
    }
}

// ---------------------------------------------------------------------------
// Tensor-core window attention, register-resident softmax (FA2 passthrough).
// One block (128 thr, 4 warps) per (window, head). Warp owns 16 rows.
// ---------------------------------------------------------------------------
__global__ __launch_bounds__(128) void attn_kernel(
    const __half* __restrict__ qkv, const float* __restrict__ bias,
    __half* __restrict__ out)
{
    int b = blockIdx.x / HEADS;
    int h = blockIdx.x % HEADS;
    int tid = threadIdx.x, lane = tid & 31, wid = tid >> 5;

    __shared__ __half sQ[64 * 32], sK[64 * 32], sVt[32 * 64];
    __shared__ float sB[NTOK * NTOK];

    // zero sVt (cols >= NTOK must be exactly 0)
    for (int i = tid; i < 256; i += 128) ((uint4*)sVt)[i] = make_uint4(0, 0, 0, 0);
    __syncthreads();

    // load q, k, v (vectorized) + bias table to smem
    const __half* base = qkv + (size_t)b * NTOK * (3 * DIM);
    for (int idx = tid; idx < NTOK * HD / 4; idx += 128) {
        int n = idx >> 3, dc = idx & 7;
        int d = dc * 4;
        const __half* tp = base + n * (3 * DIM) + h * HD + d;
        uint2 qv = *(const uint2*)tp;
        uint2 kv = *(const uint2*)(tp + DIM);
        uint2 vv = *(const uint2*)(tp + 2 * DIM);
        uint32_t qoff = n * 64 + ((((d >> 3) ^ (n & 3))) << 4) + (d & 7) * 2;
        *(uint2*)((char*)sQ + qoff) = qv;
        *(uint2*)((char*)sK + qoff) = kv;
        const __half* vp = (const __half*)&vv;
        #pragma unroll
        for (int e = 0; e < 4; e++) {
            int dd = d + e;
            uint32_t voff = dd * 128 + ((((n >> 3) ^ (dd & 7))) << 4) + (n & 7) * 2;
            *(__half*)((char*)sVt + voff) = vp[e];
        }
    }
    const float* bb = bias + h * NTOK * NTOK;
    for (int i = tid; i < NTOK * NTOK; i += 128) sB[i] = bb[i];
    __syncthreads();

    uint32_t sqb = smem_u32(sQ), skb = smem_u32(sK), svb = smem_u32(sVt);

    // ---- S = Q K^T kept in registers: sfull[nt][n8][e] ----
    float sfull[4][2][4];
    {
        uint32_t a[2][4];
        #pragma unroll
        for (int kk = 0; kk < 2; kk++) {
            int ra = wid * 16 + (lane & 15);
            int kga = kk * 2 + (lane >> 4);
            ldmx4(a[kk], sqb + ra * 64 + ((kga ^ (ra & 3)) << 4));
        }
        #pragma unroll
        for (int nt = 0; nt < 4; nt++) {
            #pragma unroll
            for (int n8 = 0; n8 < 2; n8++)
                #pragma unroll
                for (int e = 0; e < 4; e++) sfull[nt][n8][e] = 0.f;
            #pragma unroll
            for (int kk = 0; kk < 2; kk++) {
                uint32_t bf[4];
                int nb = nt * 16 + (lane & 7) + ((lane >> 4) << 3);
                int kgb = kk * 2 + ((lane >> 3) & 1);
                ldmx4(bf, skb + nb * 64 + ((kgb ^ (nb & 3)) << 4));
                mma_f16(sfull[nt][0], a[kk], bf[0], bf[1]);
                mma_f16(sfull[nt][1], a[kk], bf[2], bf[3]);
            }
        }
    }

    // ---- register softmax (rows r0 and r0+8 per lane) ----
    const float scale = 0.17677669529663687f;
    int r0 = lane >> 2;
    float mx[2] = {-1e30f, -1e30f};
    #pragma unroll
    for (int nt = 0; nt < 4; nt++)
        #pragma unroll
        for (int n8 = 0; n8 < 2; n8++)
            #pragma unroll
            for (int e = 0; e < 4; e++) {
                int i = wid * 16 + r0 + (e >> 1) * 8;
                int j = nt * 16 + n8 * 8 + (lane & 3) * 2 + (e & 1);
                float v = (i < NTOK && j < NTOK)
                          ? sfull[nt][n8][e] * scale + sB[i * NTOK + j] : -1e30f;
                sfull[nt][n8][e] = v;
                mx[e >> 1] = fmaxf(mx[e >> 1], v);
            }
    #pragma unroll
    for (int o = 1; o <= 2; o <<= 1) {
        mx[0] = fmaxf(mx[0], __shfl_xor_sync(0xffffffffu, mx[0], o));
        mx[1] = fmaxf(mx[1], __shfl_xor_sync(0xffffffffu, mx[1], o));
    }
    float sum[2] = {0.f, 0.f};
    #pragma unroll
    for (int nt = 0; nt < 4; nt++)
        #pragma unroll
        for (int n8 = 0; n8 < 2; n8++)
            #pragma unroll
            for (int e = 0; e < 4; e++) {
                float ev = __expf(sfull[nt][n8][e] - mx[e >> 1]);
                sfull[nt][n8][e] = ev;
                sum[e >> 1] += ev;
            }
    #pragma unroll
    for (int o = 1; o <= 2; o <<= 1) {
        sum[0] += __shfl_xor_sync(0xffffffffu, sum[0], o);
        sum[1] += __shfl_xor_sync(0xffffffffu, sum[1], o);
    }
    float inv0 = 1.0f / sum[0], inv1 = 1.0f / sum[1];

    // ---- pack P fragments (C-layout == A-layout passthrough) ----
    uint32_t pf[4][4];
    #pragma unroll
    for (int kt = 0; kt < 4; kt++) {
        __half2 h0 = __floats2half2_rn(sfull[kt][0][0] * inv0, sfull[kt][0][1] * inv0);
        __half2 h1 = __floats2half2_rn(sfull[kt][0][2] * inv1, sfull[kt][0][3] * inv1);
        __half2 h2 = __floats2half2_rn(sfull[kt][1][0] * inv0, sfull[kt][1][1] * inv0);
        __half2 h3 = __floats2half2_rn(sfull[kt][1][2] * inv1, sfull[kt][1][3] * inv1);
        pf[kt][0] = *(uint32_t*)&h0;
        pf[kt][1] = *(uint32_t*)&h1;
        pf[kt][2] = *(uint32_t*)&h2;
        pf[kt][3] = *(uint32_t*)&h3;
    }

    // ---- O = P V (A from registers, B from sVt) ----
    float co[2][2][4] = {};
    #pragma unroll
    for (int kt = 0; kt < 4; kt++) {
        #pragma unroll
        for (int nt = 0; nt < 2; nt++) {
            uint32_t bf[4];
            int nb = nt * 16 + (lane & 7) + ((lane >> 4) << 3);
            int kgb = kt * 2 + ((lane >> 3) & 1);
            ldmx4(bf, svb + nb * 128 + ((kgb ^ (nb & 7)) << 4));
            mma_f16(co[nt][0], pf[kt], bf[0], bf[1]);
            mma_f16(co[nt][1], pf[kt], bf[2], bf[3]);
        }
    }
    #pragma unroll
    for (int nt = 0; nt < 2; nt++)
        #pragma unroll
        for (int n8 = 0; n8 < 2; n8++)
            #pragma unroll
            for (int hf = 0; hf < 2; hf++) {
                int row = wid * 16 + r0 + hf * 8;
                if (row < NTOK) {
                    int col = nt * 16 + n8 * 8 + (lane & 3) * 2;
                    __half2 hv;
                    hv.x = __float2half_rn(co[nt][n8][hf * 2]);
                    hv.y = __float2half_rn(co[nt][n8][hf * 2 + 1]);
                    *(__half2*)(out + ((size_t)b * NTOK + row) * DIM + h * HD + col) = hv;
                }
            }
}

// ---------------------------------------------------------------------------
// Launch
// ---------------------------------------------------------------------------
extern "C" void kernel_launch(void* const* d_in, const int* in_sizes, int n_in,
                              void* d_out, int out_size)
{
    const float* x          = (const float*)d_in[0];
    const float* ln1_g      = (const float*)d_in[1];
    const float* ln1_b      = (const float*)d_in[2];
    const float* qkv_w      = (const float*)d_in[3];
    const float* proj_w     = (const float*)d_in[4];
    const float* proj_b     = (const float*)d_in[5];
    const float* bias_table = (const float*)d_in[6];
    const float* ln2_g      = (const float*)d_in[7];
    const float* ln2_b      = (const float*)d_in[8];
    const float* fc1_w      = (const float*)d_in[9];
    const float* fc1_b      = (const float*)d_in[10];
    const float* fc2_w      = (const float*)d_in[11];
    const float* fc2_b      = (const float*)d_in[12];
    const int*   rel_index  = (const int*)d_in[13];
    float* out = (float*)d_out;

    __half *act, *qkvh, *hid, *wq, *wp, *w1, *w2;
    float* biasg;
    cudaGetSymbolAddress((void**)&act, g_act192);
    cudaGetSymbolAddress((void**)&qkvh, g_qkvh);
    cudaGetSymbolAddress((void**)&hid, g_hid);
    cudaGetSymbolAddress((void**)&wq, g_wqkv);
    cudaGetSymbolAddress((void**)&wp, g_wprj);
    cudaGetSymbolAddress((void**)&w1, g_wfc1);
    cudaGetSymbolAddress((void**)&w2, g_wfc2);
    cudaGetSymbolAddress((void**)&biasg, g_bias);

    cudaFuncSetAttribute(tc_gemm<576, 192, 0>, cudaFuncAttributeMaxDynamicSharedMemorySize, GEMM_SMEM);
    cudaFuncSetAttribute(tc_gemm<192, 192, 3>, cudaFuncAttributeMaxDynamicSharedMemorySize, GEMM_SMEM);
    cudaFuncSetAttribute(tc_gemm<768, 192, 2>, cudaFuncAttributeMaxDynamicSharedMemorySize, GEMM_SMEM);
    cudaFuncSetAttribute(tc_gemm<192, 768, 1>, cudaFuncAttributeMaxDynamicSharedMemorySize, GEMM_SMEM);

    // launch 1: all prep
    prep_all<<<894, 512>>>(qkv_w, wq, proj_w, wp, fc1_w, w1, fc2_w, w2,
                           bias_table, rel_index, biasg);
    // launch 2: LN1
    ln_kernel<<<MROWS, DIM>>>(x, ln1_g, ln1_b, act);
    // launch 3: qkv GEMM
    {
        dim3 grid(3, MROWS / 128);
        tc_gemm<576, 192, 0><<<grid, 512, GEMM_SMEM>>>(act, wq, nullptr, nullptr,
                                                       nullptr, qkvh, nullptr, nullptr);
    }
    // launch 4: attention
    attn_kernel<<<BW * HEADS, 128>>>(qkvh, biasg, act);
    // launch 5: proj + residual + fused LN2
    {
        dim3 grid(1, MROWS / 128);
        tc_gemm<192, 192, 3><<<grid, 512, GEMM_SMEM>>>(act, wp, proj_b, x,
                                                       out, act, ln2_g, ln2_b);
    }
    // launch 6: fc1 + GELU
    {
        dim3 grid(4, MROWS / 128);
        tc_gemm<768, 192, 2><<<grid, 512, GEMM_SMEM>>>(act, w1, fc1_b, nullptr,
                                                       nullptr, hid, nullptr, nullptr);
    }
    // launch 7: fc2 + residual
    {
        dim3 grid(1, MROWS / 128);
        tc_gemm<192, 768, 1><<<grid, 512, GEMM_SMEM>>>(hid, w2, fc2_b, out,
                                                       out, nullptr, nullptr, nullptr);
    }
}

// round 13
// speedup vs baseline: 1.7226x; 1.1148x over previous
#include <cuda_runtime.h>
#include <cuda_fp16.h>
#include <math.h>
#include <stdint.h>

#define BW    4096
#define NTOK  49
#define DIM   192
#define HEADS 6
#define HD    32
#define HIDDEN 768
#define MROWS (BW * NTOK)   // 200704

// ---------------------------------------------------------------------------
// Scratch (allocation-free, __device__ globals)
// ---------------------------------------------------------------------------
__device__ __half g_act192[(size_t)MROWS * DIM];
__device__ __half g_qkvh[(size_t)MROWS * 3 * DIM];
__device__ __half g_hid[(size_t)MROWS * HIDDEN];

__device__ __half g_wqkv[3 * DIM * DIM];
__device__ __half g_wprj[DIM * DIM];
__device__ __half g_wfc1[DIM * HIDDEN];
__device__ __half g_wfc2[HIDDEN * DIM];
__device__ __half g_bias[HEADS * NTOK * NTOK];   // fp16 pre-gathered bias

// ---------------------------------------------------------------------------
// helpers
// ---------------------------------------------------------------------------
__device__ __forceinline__ uint32_t smem_u32(const void* p) {
    uint32_t a;
    asm("{ .reg .u64 t; cvta.to.shared.u64 t, %1; cvt.u32.u64 %0, t; }" : "=r"(a) : "l"(p));
    return a;
}
__device__ __forceinline__ void cpa16(uint32_t dst, const void* src) {
    asm volatile("cp.async.cg.shared.global [%0], [%1], 16;" :: "r"(dst), "l"(src));
}
__device__ __forceinline__ void cp_commit() {
    asm volatile("cp.async.commit_group;" ::: "memory");
}
__device__ __forceinline__ void cp_wait1() {
    asm volatile("cp.async.wait_group 1;" ::: "memory");
}
__device__ __forceinline__ void ldmx4(uint32_t* r, uint32_t addr) {
    asm volatile("ldmatrix.sync.aligned.m8n8.x4.shared.b16 {%0,%1,%2,%3}, [%4];"
                 : "=r"(r[0]), "=r"(r[1]), "=r"(r[2]), "=r"(r[3]) : "r"(addr));
}
__device__ __forceinline__ void ldmx4t(uint32_t* r, uint32_t addr) {
    asm volatile("ldmatrix.sync.aligned.m8n8.x4.trans.shared.b16 {%0,%1,%2,%3}, [%4];"
                 : "=r"(r[0]), "=r"(r[1]), "=r"(r[2]), "=r"(r[3]) : "r"(addr));
}
__device__ __forceinline__ void mma_f16(float* c, const uint32_t* a,
                                        uint32_t b0, uint32_t b1) {
    asm volatile(
        "mma.sync.aligned.m16n8k16.row.col.f32.f16.f16.f32 "
        "{%0,%1,%2,%3}, {%4,%5,%6,%7}, {%8,%9}, {%0,%1,%2,%3};"
        : "+f"(c[0]), "+f"(c[1]), "+f"(c[2]), "+f"(c[3])
        : "r"(a[0]), "r"(a[1]), "r"(a[2]), "r"(a[3]), "r"(b0), "r"(b1));
}

// ---------------------------------------------------------------------------
// One merged prep kernel
// ---------------------------------------------------------------------------
#define PQ  (DIM * 576)
#define PP  (DIM * DIM)
#define P1  (DIM * HIDDEN)
#define P2  (HIDDEN * DIM)
#define PB  (HEADS * NTOK * NTOK)
#define PTOT (PQ + PP + P1 + P2 + PB)

__global__ void prep_all(
    const float* __restrict__ Wq, __half* __restrict__ Wqt,
    const float* __restrict__ Wp, __half* __restrict__ Wpt,
    const float* __restrict__ W1, __half* __restrict__ W1t,
    const float* __restrict__ W2, __half* __restrict__ W2t,
    const float* __restrict__ table, const int* __restrict__ ridx,
    __half* __restrict__ biasg)
{
    for (int idx = blockIdx.x * blockDim.x + threadIdx.x; idx < PTOT;
         idx += gridDim.x * blockDim.x) {
        if (idx < PQ) {
            int k = idx / 576, n = idx - k * 576;
            Wqt[(size_t)n * DIM + k] = __float2half_rn(Wq[idx]);
        } else if (idx < PQ + PP) {
            int i = idx - PQ;
            int k = i / DIM, n = i - k * DIM;
            Wpt[(size_t)n * DIM + k] = __float2half_rn(Wp[i]);
        } else if (idx < PQ + PP + P1) {
            int i = idx - PQ - PP;
            int k = i / HIDDEN, n = i - k * HIDDEN;
            W1t[(size_t)n * DIM + k] = __float2half_rn(W1[i]);
        } else if (idx < PQ + PP + P1 + P2) {
            int i = idx - PQ - PP - P1;
            int k = i / DIM, n = i - k * DIM;
            W2t[(size_t)n * HIDDEN + k] = __float2half_rn(W2[i]);
        } else {
            int i = idx - PQ - PP - P1 - P2;
            int h = i / (NTOK * NTOK), ij = i % (NTOK * NTOK);
            biasg[i] = __float2half_rn(table[ridx[ij] * HEADS + h]);
        }
    }
}

// ---------------------------------------------------------------------------
// LayerNorm -> fp16: warp per row, 8 rows per 256-thread block, pure shfl.
// ---------------------------------------------------------------------------
__global__ __launch_bounds__(256) void ln_kernel(
    const float* __restrict__ x, const float* __restrict__ g,
    const float* __restrict__ b, __half* __restrict__ o)
{
    int row = blockIdx.x * 8 + (threadIdx.x >> 5);
    int lane = threadIdx.x & 31;
    const float* xp = x + (size_t)row * DIM;
    float v[6];
    float s = 0.f, s2 = 0.f;
    #pragma unroll
    for (int i = 0; i < 6; i++) {
        v[i] = xp[lane + 32 * i];
        s += v[i];
        s2 += v[i] * v[i];
    }
    #pragma unroll
    for (int of = 16; of > 0; of >>= 1) {
        s  += __shfl_xor_sync(0xffffffffu, s,  of);
        s2 += __shfl_xor_sync(0xffffffffu, s2, of);
    }
    float mu = s * (1.0f / DIM);
    float var = s2 * (1.0f / DIM) - mu * mu;
    float rstd = rsqrtf(var + 1e-5f);
    __half* op = o + (size_t)row * DIM;
    #pragma unroll
    for (int i = 0; i < 6; i++) {
        int c = lane + 32 * i;
        op[c] = __float2half_rn((v[i] - mu) * rstd * g[c] + b[c]);
    }
}

// ---------------------------------------------------------------------------
// fp16 HMMA GEMM (unchanged R10/R12 config)
// ---------------------------------------------------------------------------
#define STAGE   20480u
#define O_B     8192u
#define GEMM_SMEM (3 * 20480)

template <int N_TOTAL, int K_TOTAL, int EPI>
__global__ __launch_bounds__(512, 1) void tc_gemm(
    const __half* __restrict__ A, const __half* __restrict__ B,
    const float* __restrict__ bias, const float* __restrict__ res,
    float* __restrict__ Cf, __half* __restrict__ Ch,
    const float* __restrict__ lng, const float* __restrict__ lnb)
{
    constexpr int KSTEPS = K_TOTAL / 32;

    extern __shared__ char smem[];
    __shared__ float s_red[128 * 8];
    uint32_t sb = smem_u32(smem);
    int tid = threadIdx.x, lane = tid & 31, wid = tid >> 5;
    int wm = wid & 3, wn = wid >> 2;
    size_t rowbase = (size_t)blockIdx.y * 128;
    int colbase = blockIdx.x * 192;

    auto load_stage = [&](int s) {
        uint32_t base = sb + (uint32_t)(s % 3) * STAGE;
        {
            int r = tid >> 2, kg = tid & 3;
            uint32_t soff = r * 64 + ((kg ^ (r & 3)) << 4);
            cpa16(base + soff, A + (rowbase + r) * K_TOTAL + s * 32 + kg * 8);
        }
        #pragma unroll
        for (int i = tid; i < 768; i += 512) {
            int r = i >> 2, kg = i & 3;
            uint32_t soff = r * 64 + ((kg ^ (r & 3)) << 4);
            cpa16(base + O_B + soff, B + (size_t)(colbase + r) * K_TOTAL + s * 32 + kg * 8);
        }
    };

    uint32_t aoff[2][2], boff[3][2];
    #pragma unroll
    for (int mt = 0; mt < 2; mt++)
        #pragma unroll
        for (int kk = 0; kk < 2; kk++) {
            int ra = wm * 32 + mt * 16 + (lane & 15);
            int kga = kk * 2 + (lane >> 4);
            aoff[mt][kk] = ra * 64 + ((kga ^ (ra & 3)) << 4);
        }
    #pragma unroll
    for (int np = 0; np < 3; np++)
        #pragma unroll
        for (int kk = 0; kk < 2; kk++) {
            int nb = wn * 48 + np * 16 + (lane & 7) + ((lane >> 4) << 3);
            int kgb = kk * 2 + ((lane >> 3) & 1);
            boff[np][kk] = nb * 64 + ((kgb ^ (nb & 3)) << 4);
        }

    float acc[2][6][4] = {};

    load_stage(0); cp_commit();
    load_stage(1); cp_commit();

    for (int s = 0; s < KSTEPS; s++) {
        cp_wait1();
        __syncthreads();
        if (s + 2 < KSTEPS) load_stage(s + 2);
        cp_commit();
        uint32_t base = sb + (uint32_t)(s % 3) * STAGE;
        #pragma unroll
        for (int kk = 0; kk < 2; kk++) {
            uint32_t ah[2][4];
            ldmx4(ah[0], base + aoff[0][kk]);
            ldmx4(ah[1], base + aoff[1][kk]);
            #pragma unroll
            for (int np = 0; np < 3; np++) {
                uint32_t bf[4];
                ldmx4(bf, base + O_B + boff[np][kk]);
                #pragma unroll
                for (int mt = 0; mt < 2; mt++) {
                    mma_f16(acc[mt][np * 2],     ah[mt], bf[0], bf[1]);
                    mma_f16(acc[mt][np * 2 + 1], ah[mt], bf[2], bf[3]);
                }
            }
        }
    }

    if (EPI == 3) {
        float psum[2][2] = {}, psq[2][2] = {};
        #pragma unroll
        for (int mt = 0; mt < 2; mt++)
            #pragma unroll
            for (int nt = 0; nt < 6; nt++) {
                int c = colbase + wn * 48 + nt * 8 + (lane & 3) * 2;
                #pragma unroll
                for (int half = 0; half < 2; half++) {
                    size_t row = rowbase + wm * 32 + mt * 16 + (lane >> 2) + half * 8;
                    float v0 = acc[mt][nt][half * 2]     + bias[c];
                    float v1 = acc[mt][nt][half * 2 + 1] + bias[c + 1];
                    const float2 rv = *(const float2*)(res + row * N_TOTAL + c);
                    v0 += rv.x; v1 += rv.y;
                    acc[mt][nt][half * 2] = v0;
                    acc[mt][nt][half * 2 + 1] = v1;
                    psum[mt][half] += v0 + v1;
                    psq[mt][half]  += v0 * v0 + v1 * v1;
                }
            }
        #pragma unroll
        for (int o = 1; o <= 2; o <<= 1)
            #pragma unroll
            for (int mt = 0; mt < 2; mt++)
                #pragma unroll
                for (int half = 0; half < 2; half++) {
                    psum[mt][half] += __shfl_xor_sync(0xffffffffu, psum[mt][half], o);
                    psq[mt][half]  += __shfl_xor_sync(0xffffffffu, psq[mt][half],  o);
                }
        if ((lane & 3) == 0) {
            #pragma unroll
            for (int mt = 0; mt < 2; mt++)
                #pragma unroll
                for (int half = 0; half < 2; half++) {
                    int lrow = wm * 32 + mt * 16 + (lane >> 2) + half * 8;
                    s_red[lrow * 8 + wn * 2]     = psum[mt][half];
                    s_red[lrow * 8 + wn * 2 + 1] = psq[mt][half];
                }
        }
        __syncthreads();
        float mu[2][2], rs[2][2];
        #pragma unroll
        for (int mt = 0; mt < 2; mt++)
            #pragma unroll
            for (int half = 0; half < 2; half++) {
                int lrow = wm * 32 + mt * 16 + (lane >> 2) + half * 8;
                float S = 0.f, Q = 0.f;
                #pragma unroll
                for (int w = 0; w < 4; w++) {
                    S += s_red[lrow * 8 + w * 2];
                    Q += s_red[lrow * 8 + w * 2 + 1];
                }
                float m = S * (1.0f / N_TOTAL);
                float var = Q * (1.0f / N_TOTAL) - m * m;
                mu[mt][half] = m;
                rs[mt][half] = rsqrtf(var + 1e-5f);
            }
        #pragma unroll
        for (int mt = 0; mt < 2; mt++)
            #pragma unroll
            for (int nt = 0; nt < 6; nt++) {
                int c = colbase + wn * 48 + nt * 8 + (lane & 3) * 2;
                float g0 = lng[c], g1 = lng[c + 1];
                float b0 = lnb[c], b1 = lnb[c + 1];
                #pragma unroll
                for (int half = 0; half < 2; half++) {
                    size_t row = rowbase + wm * 32 + mt * 16 + (lane >> 2) + half * 8;
                    float v0 = acc[mt][nt][half * 2];
                    float v1 = acc[mt][nt][half * 2 + 1];
                    float2 ov; ov.x = v0; ov.y = v1;
                    *(float2*)(Cf + row * N_TOTAL + c) = ov;
                    float n0 = (v0 - mu[mt][half]) * rs[mt][half] * g0 + b0;
                    float n1 = (v1 - mu[mt][half]) * rs[mt][half] * g1 + b1;
                    __half2 hv; hv.x = __float2half_rn(n0); hv.y = __float2half_rn(n1);
                    *(__half2*)(Ch + row * N_TOTAL + c) = hv;
                }
            }
    } else {
        #pragma unroll
        for (int mt = 0; mt < 2; mt++) {
            size_t rbase = rowbase + wm * 32 + mt * 16 + (lane >> 2);
            #pragma unroll
            for (int nt = 0; nt < 6; nt++) {
                int c = colbase + wn * 48 + nt * 8 + (lane & 3) * 2;
                #pragma unroll
                for (int half = 0; half < 2; half++) {
                    size_t row = rbase + half * 8;
                    float v0 = acc[mt][nt][half * 2];
                    float v1 = acc[mt][nt][half * 2 + 1];
                    if (EPI >= 1) { v0 += bias[c]; v1 += bias[c + 1]; }
                    if (EPI == 2) {
                        v0 = 0.5f * v0 * (1.0f + erff(v0 * 0.70710678118654752f));
                        v1 = 0.5f * v1 * (1.0f + erff(v1 * 0.70710678118654752f));
                    }
                    if (EPI == 1) {
                        const float2 rv = *(const float2*)(res + row * N_TOTAL + c);
                        float2 ov; ov.x = v0 + rv.x; ov.y = v1 + rv.y;
                        *(float2*)(Cf + row * N_TOTAL + c) = ov;
                    } else {
                        __half2 hv; hv.x = __float2half_rn(v0); hv.y = __float2half_rn(v1);
                        *(__half2*)(Ch + row * N_TOTAL + c) = hv;
                    }
                }
            }
        }
    }
}

// ---------------------------------------------------------------------------
// Tensor-core window attention: register softmax + ldmatrix.trans V loads.
// One block (128 thr, 4 warps) per (window, head). Warp owns 16 rows.
// ---------------------------------------------------------------------------
__global__ __launch_bounds__(128) void attn_kernel(
    const __half* __restrict__ qkv, const __half* __restrict__ bias,
    __half* __restrict__ out)
{
    int b = blockIdx.x / HEADS;
    int h = blockIdx.x % HEADS;
    int tid = threadIdx.x, lane = tid & 31, wid = tid >> 5;

    __shared__ __half sQ[64 * 32], sK[64 * 32], sV[64 * 32];
    __shared__ __half sB[NTOK * NTOK + 1];

    // zero sV only (P==0 at masked j, but V must be finite)
    for (int i = tid; i < 256; i += 128) ((uint4*)sV)[i] = make_uint4(0, 0, 0, 0);
    __syncthreads();

    // vectorized loads of q, k, v (identical swizzled row-major layout)
    const __half* base = qkv + (size_t)b * NTOK * (3 * DIM);
    for (int idx = tid; idx < NTOK * HD / 4; idx += 128) {
        int n = idx >> 3, dc = idx & 7;
        int d = dc * 4;
        const __half* tp = base + n * (3 * DIM) + h * HD + d;
        uint2 qv = *(const uint2*)tp;
        uint2 kv = *(const uint2*)(tp + DIM);
        uint2 vv = *(const uint2*)(tp + 2 * DIM);
        uint32_t off = n * 64 + ((((d >> 3) ^ (n & 3))) << 4) + (d & 7) * 2;
        *(uint2*)((char*)sQ + off) = qv;
        *(uint2*)((char*)sK + off) = kv;
        *(uint2*)((char*)sV + off) = vv;
    }
    const __half* bb = bias + h * NTOK * NTOK;
    for (int i = tid; i < NTOK * NTOK; i += 128) sB[i] = bb[i];
    __syncthreads();

    uint32_t sqb = smem_u32(sQ), skb = smem_u32(sK), svb = smem_u32(sV);

    // ---- S = Q K^T in registers ----
    float sfull[4][2][4];
    {
        uint32_t a[2][4];
        #pragma unroll
        for (int kk = 0; kk < 2; kk++) {
            int ra = wid * 16 + (lane & 15);
            int kga = kk * 2 + (lane >> 4);
            ldmx4(a[kk], sqb + ra * 64 + ((kga ^ (ra & 3)) << 4));
        }
        #pragma unroll
        for (int nt = 0; nt < 4; nt++) {
            #pragma unroll
            for (int n8 = 0; n8 < 2; n8++)
                #pragma unroll
                for (int e = 0; e < 4; e++) sfull[nt][n8][e] = 0.f;
            #pragma unroll
            for (int kk = 0; kk < 2; kk++) {
                uint32_t bf[4];
                int nb = nt * 16 + (lane & 7) + ((lane >> 4) << 3);
                int kgb = kk * 2 + ((lane >> 3) & 1);
                ldmx4(bf, skb + nb * 64 + ((kgb ^ (nb & 3)) << 4));
                mma_f16(sfull[nt][0], a[kk], bf[0], bf[1]);
                mma_f16(sfull[nt][1], a[kk], bf[2], bf[3]);
            }
        }
    }

    // ---- register softmax ----
    const float scale = 0.17677669529663687f;
    int r0 = lane >> 2;
    float mx[2] = {-1e30f, -1e30f};
    #pragma unroll
    for (int nt = 0; nt < 4; nt++)
        #pragma unroll
        for (int n8 = 0; n8 < 2; n8++)
            #pragma unroll
            for (int e = 0; e < 4; e++) {
                int i = wid * 16 + r0 + (e >> 1) * 8;
                int j = nt * 16 + n8 * 8 + (lane & 3) * 2 + (e & 1);
                float v = (i < NTOK && j < NTOK)
                          ? sfull[nt][n8][e] * scale + __half2float(sB[i * NTOK + j])
                          : -1e30f;
                sfull[nt][n8][e] = v;
                mx[e >> 1] = fmaxf(mx[e >> 1], v);
            }
    #pragma unroll
    for (int o = 1; o <= 2; o <<= 1) {
        mx[0] = fmaxf(mx[0], __shfl_xor_sync(0xffffffffu, mx[0], o));
        mx[1] = fmaxf(mx[1], __shfl_xor_sync(0xffffffffu, mx[1], o));
    }
    float sum[2] = {0.f, 0.f};
    #pragma unroll
    for (int nt = 0; nt < 4; nt++)
        #pragma unroll
        for (int n8 = 0; n8 < 2; n8++)
            #pragma unroll
            for (int e = 0; e < 4; e++) {
                float ev = __expf(sfull[nt][n8][e] - mx[e >> 1]);
                sfull[nt][n8][e] = ev;
                sum[e >> 1] += ev;
            }
    #pragma unroll
    for (int o = 1; o <= 2; o <<= 1) {
        sum[0] += __shfl_xor_sync(0xffffffffu, sum[0], o);
        sum[1] += __shfl_xor_sync(0xffffffffu, sum[1], o);
    }
    float inv0 = 1.0f / sum[0], inv1 = 1.0f / sum[1];

    // ---- pack P fragments (C-layout == A-layout passthrough) ----
    uint32_t pf[4][4];
    #pragma unroll
    for (int kt = 0; kt < 4; kt++) {
        __half2 h0 = __floats2half2_rn(sfull[kt][0][0] * inv0, sfull[kt][0][1] * inv0);
        __half2 h1 = __floats2half2_rn(sfull[kt][0][2] * inv1, sfull[kt][0][3] * inv1);
        __half2 h2 = __floats2half2_rn(sfull[kt][1][0] * inv0, sfull[kt][1][1] * inv0);
        __half2 h3 = __floats2half2_rn(sfull[kt][1][2] * inv1, sfull[kt][1][3] * inv1);
        pf[kt][0] = *(uint32_t*)&h0;
        pf[kt][1] = *(uint32_t*)&h1;
        pf[kt][2] = *(uint32_t*)&h2;
        pf[kt][3] = *(uint32_t*)&h3;
    }

    // ---- O = P V: B-fragments via ldmatrix.trans from row-major V ----
    // V[k][n]: row = k (token j), col = n (head dim d). Trans load order:
    //   M0: rows k0-7/cols n0-7, M1: rows k8-15/cols n0-7,
    //   M2: rows k0-7/cols n8-15, M3: rows k8-15/cols n8-15.
    float co[2][2][4] = {};
    #pragma unroll
    for (int kt = 0; kt < 4; kt++) {
        #pragma unroll
        for (int nt = 0; nt < 2; nt++) {
            int row = kt * 16 + (lane & 7) + ((lane >> 3) & 1) * 8;
            int c8 = nt * 2 + (lane >> 4);
            uint32_t voff = row * 64 + ((c8 ^ (row & 3)) << 4);
            uint32_t bf[4];
            ldmx4t(bf, svb + voff);
            mma_f16(co[nt][0], pf[kt], bf[0], bf[1]);
            mma_f16(co[nt][1], pf[kt], bf[2], bf[3]);
        }
    }
    #pragma unroll
    for (int nt = 0; nt < 2; nt++)
        #pragma unroll
        for (int n8 = 0; n8 < 2; n8++)
            #pragma unroll
            for (int hf = 0; hf < 2; hf++) {
                int row = wid * 16 + r0 + hf * 8;
                if (row < NTOK) {
                    int col = nt * 16 + n8 * 8 + (lane & 3) * 2;
                    __half2 hv;
                    hv.x = __float2half_rn(co[nt][n8][hf * 2]);
                    hv.y = __float2half_rn(co[nt][n8][hf * 2 + 1]);
                    *(__half2*)(out + ((size_t)b * NTOK + row) * DIM + h * HD + col) = hv;
                }
            }
}

// ---------------------------------------------------------------------------
// Launch
// ---------------------------------------------------------------------------
extern "C" void kernel_launch(void* const* d_in, const int* in_sizes, int n_in,
                              void* d_out, int out_size)
{
    const float* x          = (const float*)d_in[0];
    const float* ln1_g      = (const float*)d_in[1];
    const float* ln1_b      = (const float*)d_in[2];
    const float* qkv_w      = (const float*)d_in[3];
    const float* proj_w     = (const float*)d_in[4];
    const float* proj_b     = (const float*)d_in[5];
    const float* bias_table = (const float*)d_in[6];
    const float* ln2_g      = (const float*)d_in[7];
    const float* ln2_b      = (const float*)d_in[8];
    const float* fc1_w      = (const float*)d_in[9];
    const float* fc1_b      = (const float*)d_in[10];
    const float* fc2_w      = (const float*)d_in[11];
    const float* fc2_b      = (const float*)d_in[12];
    const int*   rel_index  = (const int*)d_in[13];
    float* out = (float*)d_out;

    __half *act, *qkvh, *hid, *wq, *wp, *w1, *w2, *biasg;
    cudaGetSymbolAddress((void**)&act, g_act192);
    cudaGetSymbolAddress((void**)&qkvh, g_qkvh);
    cudaGetSymbolAddress((void**)&hid, g_hid);
    cudaGetSymbolAddress((void**)&wq, g_wqkv);
    cudaGetSymbolAddress((void**)&wp, g_wprj);
    cudaGetSymbolAddress((void**)&w1, g_wfc1);
    cudaGetSymbolAddress((void**)&w2, g_wfc2);
    cudaGetSymbolAddress((void**)&biasg, g_bias);

    cudaFuncSetAttribute(tc_gemm<576, 192, 0>, cudaFuncAttributeMaxDynamicSharedMemorySize, GEMM_SMEM);
    cudaFuncSetAttribute(tc_gemm<192, 192, 3>, cudaFuncAttributeMaxDynamicSharedMemorySize, GEMM_SMEM);
    cudaFuncSetAttribute(tc_gemm<768, 192, 2>, cudaFuncAttributeMaxDynamicSharedMemorySize, GEMM_SMEM);
    cudaFuncSetAttribute(tc_gemm<192, 768, 1>, cudaFuncAttributeMaxDynamicSharedMemorySize, GEMM_SMEM);

    // launch 1: all prep
    prep_all<<<894, 512>>>(qkv_w, wq, proj_w, wp, fc1_w, w1, fc2_w, w2,
                           bias_table, rel_index, biasg);
    // launch 2: LN1
    ln_kernel<<<MROWS / 8, 256>>>(x, ln1_g, ln1_b, act);
    // launch 3: qkv GEMM
    {
        dim3 grid(3, MROWS / 128);
        tc_gemm<576, 192, 0><<<grid, 512, GEMM_SMEM>>>(act, wq, nullptr, nullptr,
                                                       nullptr, qkvh, nullptr, nullptr);
    }
    // launch 4: attention
    attn_kernel<<<BW * HEADS, 128>>>(qkvh, biasg, act);
    // launch 5: proj + residual + fused LN2
    {
        dim3 grid(1, MROWS / 128);
        tc_gemm<192, 192, 3><<<grid, 512, GEMM_SMEM>>>(act, wp, proj_b, x,
                                                       out, act, ln2_g, ln2_b);
    }
    // launch 6: fc1 + GELU
    {
        dim3 grid(4, MROWS / 128);
        tc_gemm<768, 192, 2><<<grid, 512, GEMM_SMEM>>>(act, w1, fc1_b, nullptr,
                                                       nullptr, hid, nullptr, nullptr);
    }
    // launch 7: fc2 + residual
    {
        dim3 grid(1, MROWS / 128);
        tc_gemm<192, 768, 1><<<grid, 512, GEMM_SMEM>>>(hid, w2, fc2_b, out,
                                                       out, nullptr, nullptr, nullptr);
    }
}

// round 14
// speedup vs baseline: 1.7710x; 1.0281x over previous
#include <cuda_runtime.h>
#include <cuda_fp16.h>
#include <math.h>
#include <stdint.h>

#define BW    4096
#define NTOK  49
#define DIM   192
#define HEADS 6
#define HD    32
#define HIDDEN 768
#define MROWS (BW * NTOK)   // 200704

// ---------------------------------------------------------------------------
// Scratch (allocation-free, __device__ globals)
// ---------------------------------------------------------------------------
__device__ __half g_act192[(size_t)MROWS * DIM];
__device__ __half g_qkvh[(size_t)MROWS * 3 * DIM];
__device__ __half g_hid[(size_t)MROWS * HIDDEN];

__device__ __half g_wqkv[3 * DIM * DIM];
__device__ __half g_wprj[DIM * DIM];
__device__ __half g_wfc1[DIM * HIDDEN];
__device__ __half g_wfc2[HIDDEN * DIM];
__device__ __half g_bias[HEADS * 64 * 64];   // fp16 padded bias (64x64/head, -3e4 mask)

// ---------------------------------------------------------------------------
// helpers
// ---------------------------------------------------------------------------
__device__ __forceinline__ uint32_t smem_u32(const void* p) {
    uint32_t a;
    asm("{ .reg .u64 t; cvta.to.shared.u64 t, %1; cvt.u32.u64 %0, t; }" : "=r"(a) : "l"(p));
    return a;
}
__device__ __forceinline__ void cpa16(uint32_t dst, const void* src) {
    asm volatile("cp.async.cg.shared.global [%0], [%1], 16;" :: "r"(dst), "l"(src));
}
__device__ __forceinline__ void cp_commit() {
    asm volatile("cp.async.commit_group;" ::: "memory");
}
__device__ __forceinline__ void cp_wait1() {
    asm volatile("cp.async.wait_group 1;" ::: "memory");
}
__device__ __forceinline__ void ldmx4(uint32_t* r, uint32_t addr) {
    asm volatile("ldmatrix.sync.aligned.m8n8.x4.shared.b16 {%0,%1,%2,%3}, [%4];"
                 : "=r"(r[0]), "=r"(r[1]), "=r"(r[2]), "=r"(r[3]) : "r"(addr));
}
__device__ __forceinline__ void ldmx4t(uint32_t* r, uint32_t addr) {
    asm volatile("ldmatrix.sync.aligned.m8n8.x4.trans.shared.b16 {%0,%1,%2,%3}, [%4];"
                 : "=r"(r[0]), "=r"(r[1]), "=r"(r[2]), "=r"(r[3]) : "r"(addr));
}
__device__ __forceinline__ void mma_f16(float* c, const uint32_t* a,
                                        uint32_t b0, uint32_t b1) {
    asm volatile(
        "mma.sync.aligned.m16n8k16.row.col.f32.f16.f16.f32 "
        "{%0,%1,%2,%3}, {%4,%5,%6,%7}, {%8,%9}, {%0,%1,%2,%3};"
        : "+f"(c[0]), "+f"(c[1]), "+f"(c[2]), "+f"(c[3])
        : "r"(a[0]), "r"(a[1]), "r"(a[2]), "r"(a[3]), "r"(b0), "r"(b1));
}

// ---------------------------------------------------------------------------
// One merged prep kernel
// ---------------------------------------------------------------------------
#define PQ  (DIM * 576)
#define PP  (DIM * DIM)
#define P1  (DIM * HIDDEN)
#define P2  (HIDDEN * DIM)
#define PB  (HEADS * 64 * 64)
#define PTOT (PQ + PP + P1 + P2 + PB)

__global__ void prep_all(
    const float* __restrict__ Wq, __half* __restrict__ Wqt,
    const float* __restrict__ Wp, __half* __restrict__ Wpt,
    const float* __restrict__ W1, __half* __restrict__ W1t,
    const float* __restrict__ W2, __half* __restrict__ W2t,
    const float* __restrict__ table, const int* __restrict__ ridx,
    __half* __restrict__ biasg)
{
    for (int idx = blockIdx.x * blockDim.x + threadIdx.x; idx < PTOT;
         idx += gridDim.x * blockDim.x) {
        if (idx < PQ) {
            int k = idx / 576, n = idx - k * 576;
            Wqt[(size_t)n * DIM + k] = __float2half_rn(Wq[idx]);
        } else if (idx < PQ + PP) {
            int i = idx - PQ;
            int k = i / DIM, n = i - k * DIM;
            Wpt[(size_t)n * DIM + k] = __float2half_rn(Wp[i]);
        } else if (idx < PQ + PP + P1) {
            int i = idx - PQ - PP;
            int k = i / HIDDEN, n = i - k * HIDDEN;
            W1t[(size_t)n * DIM + k] = __float2half_rn(W1[i]);
        } else if (idx < PQ + PP + P1 + P2) {
            int i = idx - PQ - PP - P1;
            int k = i / DIM, n = i - k * DIM;
            W2t[(size_t)n * HIDDEN + k] = __float2half_rn(W2[i]);
        } else {
            int i = idx - PQ - PP - P1 - P2;
            int h = i >> 12, rc = i & 4095;
            int r = rc >> 6, c = rc & 63;
            float v = (r < NTOK && c < NTOK)
                      ? table[ridx[r * NTOK + c] * HEADS + h] : -30000.0f;
            biasg[i] = __float2half_rn(v);
        }
    }
}

// ---------------------------------------------------------------------------
// LayerNorm -> fp16: warp per row, 8 rows per 256-thread block, pure shfl.
// ---------------------------------------------------------------------------
__global__ __launch_bounds__(256) void ln_kernel(
    const float* __restrict__ x, const float* __restrict__ g,
    const float* __restrict__ b, __half* __restrict__ o)
{
    int row = blockIdx.x * 8 + (threadIdx.x >> 5);
    int lane = threadIdx.x & 31;
    const float* xp = x + (size_t)row * DIM;
    float v[6];
    float s = 0.f, s2 = 0.f;
    #pragma unroll
    for (int i = 0; i < 6; i++) {
        v[i] = xp[lane + 32 * i];
        s += v[i];
        s2 += v[i] * v[i];
    }
    #pragma unroll
    for (int of = 16; of > 0; of >>= 1) {
        s  += __shfl_xor_sync(0xffffffffu, s,  of);
        s2 += __shfl_xor_sync(0xffffffffu, s2, of);
    }
    float mu = s * (1.0f / DIM);
    float var = s2 * (1.0f / DIM) - mu * mu;
    float rstd = rsqrtf(var + 1e-5f);
    __half* op = o + (size_t)row * DIM;
    #pragma unroll
    for (int i = 0; i < 6; i++) {
        int c = lane + 32 * i;
        op[c] = __float2half_rn((v[i] - mu) * rstd * g[c] + b[c]);
    }
}

// ---------------------------------------------------------------------------
// fp16 HMMA GEMM (unchanged)
// ---------------------------------------------------------------------------
#define STAGE   20480u
#define O_B     8192u
#define GEMM_SMEM (3 * 20480)

template <int N_TOTAL, int K_TOTAL, int EPI>
__global__ __launch_bounds__(512, 1) void tc_gemm(
    const __half* __restrict__ A, const __half* __restrict__ B,
    const float* __restrict__ bias, const float* __restrict__ res,
    float* __restrict__ Cf, __half* __restrict__ Ch,
    const float* __restrict__ lng, const float* __restrict__ lnb)
{
    constexpr int KSTEPS = K_TOTAL / 32;

    extern __shared__ char smem[];
    __shared__ float s_red[128 * 8];
    uint32_t sb = smem_u32(smem);
    int tid = threadIdx.x, lane = tid & 31, wid = tid >> 5;
    int wm = wid & 3, wn = wid >> 2;
    size_t rowbase = (size_t)blockIdx.y * 128;
    int colbase = blockIdx.x * 192;

    auto load_stage = [&](int s) {
        uint32_t base = sb + (uint32_t)(s % 3) * STAGE;
        {
            int r = tid >> 2, kg = tid & 3;
            uint32_t soff = r * 64 + ((kg ^ (r & 3)) << 4);
            cpa16(base + soff, A + (rowbase + r) * K_TOTAL + s * 32 + kg * 8);
        }
        #pragma unroll
        for (int i = tid; i < 768; i += 512) {
            int r = i >> 2, kg = i & 3;
            uint32_t soff = r * 64 + ((kg ^ (r & 3)) << 4);
            cpa16(base + O_B + soff, B + (size_t)(colbase + r) * K_TOTAL + s * 32 + kg * 8);
        }
    };

    uint32_t aoff[2][2], boff[3][2];
    #pragma unroll
    for (int mt = 0; mt < 2; mt++)
        #pragma unroll
        for (int kk = 0; kk < 2; kk++) {
            int ra = wm * 32 + mt * 16 + (lane & 15);
            int kga = kk * 2 + (lane >> 4);
            aoff[mt][kk] = ra * 64 + ((kga ^ (ra & 3)) << 4);
        }
    #pragma unroll
    for (int np = 0; np < 3; np++)
        #pragma unroll
        for (int kk = 0; kk < 2; kk++) {
            int nb = wn * 48 + np * 16 + (lane & 7) + ((lane >> 4) << 3);
            int kgb = kk * 2 + ((lane >> 3) & 1);
            boff[np][kk] = nb * 64 + ((kgb ^ (nb & 3)) << 4);
        }

    float acc[2][6][4] = {};

    load_stage(0); cp_commit();
    load_stage(1); cp_commit();

    for (int s = 0; s < KSTEPS; s++) {
        cp_wait1();
        __syncthreads();
        if (s + 2 < KSTEPS) load_stage(s + 2);
        cp_commit();
        uint32_t base = sb + (uint32_t)(s % 3) * STAGE;
        #pragma unroll
        for (int kk = 0; kk < 2; kk++) {
            uint32_t ah[2][4];
            ldmx4(ah[0], base + aoff[0][kk]);
            ldmx4(ah[1], base + aoff[1][kk]);
            #pragma unroll
            for (int np = 0; np < 3; np++) {
                uint32_t bf[4];
                ldmx4(bf, base + O_B + boff[np][kk]);
                #pragma unroll
                for (int mt = 0; mt < 2; mt++) {
                    mma_f16(acc[mt][np * 2],     ah[mt], bf[0], bf[1]);
                    mma_f16(acc[mt][np * 2 + 1], ah[mt], bf[2], bf[3]);
                }
            }
        }
    }

    if (EPI == 3) {
        float psum[2][2] = {}, psq[2][2] = {};
        #pragma unroll
        for (int mt = 0; mt < 2; mt++)
            #pragma unroll
            for (int nt = 0; nt < 6; nt++) {
                int c = colbase + wn * 48 + nt * 8 + (lane & 3) * 2;
                #pragma unroll
                for (int half = 0; half < 2; half++) {
                    size_t row = rowbase + wm * 32 + mt * 16 + (lane >> 2) + half * 8;
                    float v0 = acc[mt][nt][half * 2]     + bias[c];
                    float v1 = acc[mt][nt][half * 2 + 1] + bias[c + 1];
                    const float2 rv = *(const float2*)(res + row * N_TOTAL + c);
                    v0 += rv.x; v1 += rv.y;
                    acc[mt][nt][half * 2] = v0;
                    acc[mt][nt][half * 2 + 1] = v1;
                    psum[mt][half] += v0 + v1;
                    psq[mt][half]  += v0 * v0 + v1 * v1;
                }
            }
        #pragma unroll
        for (int o = 1; o <= 2; o <<= 1)
            #pragma unroll
            for (int mt = 0; mt < 2; mt++)
                #pragma unroll
                for (int half = 0; half < 2; half++) {
                    psum[mt][half] += __shfl_xor_sync(0xffffffffu, psum[mt][half], o);
                    psq[mt][half]  += __shfl_xor_sync(0xffffffffu, psq[mt][half],  o);
                }
        if ((lane & 3) == 0) {
            #pragma unroll
            for (int mt = 0; mt < 2; mt++)
                #pragma unroll
                for (int half = 0; half < 2; half++) {
                    int lrow = wm * 32 + mt * 16 + (lane >> 2) + half * 8;
                    s_red[lrow * 8 + wn * 2]     = psum[mt][half];
                    s_red[lrow * 8 + wn * 2 + 1] = psq[mt][half];
                }
        }
        __syncthreads();
        float mu[2][2], rs[2][2];
        #pragma unroll
        for (int mt = 0; mt < 2; mt++)
            #pragma unroll
            for (int half = 0; half < 2; half++) {
                int lrow = wm * 32 + mt * 16 + (lane >> 2) + half * 8;
                float S = 0.f, Q = 0.f;
                #pragma unroll
                for (int w = 0; w < 4; w++) {
                    S += s_red[lrow * 8 + w * 2];
                    Q += s_red[lrow * 8 + w * 2 + 1];
                }
                float m = S * (1.0f / N_TOTAL);
                float var = Q * (1.0f / N_TOTAL) - m * m;
                mu[mt][half] = m;
                rs[mt][half] = rsqrtf(var + 1e-5f);
            }
        #pragma unroll
        for (int mt = 0; mt < 2; mt++)
            #pragma unroll
            for (int nt = 0; nt < 6; nt++) {
                int c = colbase + wn * 48 + nt * 8 + (lane & 3) * 2;
                float g0 = lng[c], g1 = lng[c + 1];
                float b0 = lnb[c], b1 = lnb[c + 1];
                #pragma unroll
                for (int half = 0; half < 2; half++) {
                    size_t row = rowbase + wm * 32 + mt * 16 + (lane >> 2) + half * 8;
                    float v0 = acc[mt][nt][half * 2];
                    float v1 = acc[mt][nt][half * 2 + 1];
                    float2 ov; ov.x = v0; ov.y = v1;
                    *(float2*)(Cf + row * N_TOTAL + c) = ov;
                    float n0 = (v0 - mu[mt][half]) * rs[mt][half] * g0 + b0;
                    float n1 = (v1 - mu[mt][half]) * rs[mt][half] * g1 + b1;
                    __half2 hv; hv.x = __float2half_rn(n0); hv.y = __float2half_rn(n1);
                    *(__half2*)(Ch + row * N_TOTAL + c) = hv;
                }
            }
    } else {
        #pragma unroll
        for (int mt = 0; mt < 2; mt++) {
            size_t rbase = rowbase + wm * 32 + mt * 16 + (lane >> 2);
            #pragma unroll
            for (int nt = 0; nt < 6; nt++) {
                int c = colbase + wn * 48 + nt * 8 + (lane & 3) * 2;
                #pragma unroll
                for (int half = 0; half < 2; half++) {
                    size_t row = rbase + half * 8;
                    float v0 = acc[mt][nt][half * 2];
                    float v1 = acc[mt][nt][half * 2 + 1];
                    if (EPI >= 1) { v0 += bias[c]; v1 += bias[c + 1]; }
                    if (EPI == 2) {
                        v0 = 0.5f * v0 * (1.0f + erff(v0 * 0.70710678118654752f));
                        v1 = 0.5f * v1 * (1.0f + erff(v1 * 0.70710678118654752f));
                    }
                    if (EPI == 1) {
                        const float2 rv = *(const float2*)(res + row * N_TOTAL + c);
                        float2 ov; ov.x = v0 + rv.x; ov.y = v1 + rv.y;
                        *(float2*)(Cf + row * N_TOTAL + c) = ov;
                    } else {
                        __half2 hv; hv.x = __float2half_rn(v0); hv.y = __float2half_rn(v1);
                        *(__half2*)(Ch + row * N_TOTAL + c) = hv;
                    }
                }
            }
        }
    }
}

// ---------------------------------------------------------------------------
// Tensor-core window attention: register softmax + fragment bias (no masks).
// One block (128 thr, 4 warps) per (window, head). Warp owns 16 rows.
// ---------------------------------------------------------------------------
__global__ __launch_bounds__(128) void attn_kernel(
    const __half* __restrict__ qkv, const __half* __restrict__ bias,
    __half* __restrict__ out)
{
    int b = blockIdx.x / HEADS;
    int h = blockIdx.x % HEADS;
    int tid = threadIdx.x, lane = tid & 31, wid = tid >> 5;

    __shared__ __half sQ[64 * 32], sK[64 * 32], sV[64 * 32];
    __shared__ __half sBp[64 * 64];

    // zero Q/K/V (padded rows must be finite; bias padding handles masking)
    for (int i = tid; i < 256; i += 128) {
        ((uint4*)sQ)[i] = make_uint4(0, 0, 0, 0);
        ((uint4*)sK)[i] = make_uint4(0, 0, 0, 0);
        ((uint4*)sV)[i] = make_uint4(0, 0, 0, 0);
    }
    __syncthreads();

    // vectorized loads of q, k, v (identical swizzled row-major layout)
    const __half* base = qkv + (size_t)b * NTOK * (3 * DIM);
    for (int idx = tid; idx < NTOK * HD / 4; idx += 128) {
        int n = idx >> 3, dc = idx & 7;
        int d = dc * 4;
        const __half* tp = base + n * (3 * DIM) + h * HD + d;
        uint2 qv = *(const uint2*)tp;
        uint2 kv = *(const uint2*)(tp + DIM);
        uint2 vv = *(const uint2*)(tp + 2 * DIM);
        uint32_t off = n * 64 + ((((d >> 3) ^ (n & 3))) << 4) + (d & 7) * 2;
        *(uint2*)((char*)sQ + off) = qv;
        *(uint2*)((char*)sK + off) = kv;
        *(uint2*)((char*)sV + off) = vv;
    }
    // padded bias tile -> swizzled smem (coalesced uint4)
    {
        const uint4* bb = (const uint4*)(bias + (size_t)h * 64 * 64);
        #pragma unroll
        for (int j = 0; j < 4; j++) {
            int idx = tid + j * 128;           // 512 uint4 total
            int r = idx >> 3, c8 = idx & 7;
            uint32_t off = r * 128 + ((c8 ^ (r & 7)) << 4);
            *(uint4*)((char*)sBp + off) = bb[idx];
        }
    }
    __syncthreads();

    uint32_t sqb = smem_u32(sQ), skb = smem_u32(sK), svb = smem_u32(sV);
    uint32_t sbb = smem_u32(sBp);

    // ---- S = Q K^T in registers ----
    float sfull[4][2][4];
    {
        uint32_t a[2][4];
        #pragma unroll
        for (int kk = 0; kk < 2; kk++) {
            int ra = wid * 16 + (lane & 15);
            int kga = kk * 2 + (lane >> 4);
            ldmx4(a[kk], sqb + ra * 64 + ((kga ^ (ra & 3)) << 4));
        }
        #pragma unroll
        for (int nt = 0; nt < 4; nt++) {
            #pragma unroll
            for (int n8 = 0; n8 < 2; n8++)
                #pragma unroll
                for (int e = 0; e < 4; e++) sfull[nt][n8][e] = 0.f;
            #pragma unroll
            for (int kk = 0; kk < 2; kk++) {
                uint32_t bf[4];
                int nb = nt * 16 + (lane & 7) + ((lane >> 4) << 3);
                int kgb = kk * 2 + ((lane >> 3) & 1);
                ldmx4(bf, skb + nb * 64 + ((kgb ^ (nb & 3)) << 4));
                mma_f16(sfull[nt][0], a[kk], bf[0], bf[1]);
                mma_f16(sfull[nt][1], a[kk], bf[2], bf[3]);
            }
        }
    }

    // ---- bias fragments (A-layout == C-layout of S) ----
    uint32_t bfr[4][4];
    #pragma unroll
    for (int nt = 0; nt < 4; nt++) {
        int ra = wid * 16 + (lane & 15);
        int c8 = nt * 2 + (lane >> 4);
        ldmx4(bfr[nt], sbb + ra * 128 + ((c8 ^ (ra & 7)) << 4));
    }

    // ---- register softmax (no masks: bias padding = -3e4) ----
    const float scale = 0.17677669529663687f;
    int r0 = lane >> 2;
    float mx[2] = {-1e30f, -1e30f};
    #pragma unroll
    for (int nt = 0; nt < 4; nt++)
        #pragma unroll
        for (int n8 = 0; n8 < 2; n8++) {
            float2 blo = __half22float2(*(__half2*)&bfr[nt][n8 * 2]);
            float2 bhi = __half22float2(*(__half2*)&bfr[nt][n8 * 2 + 1]);
            float v0 = sfull[nt][n8][0] * scale + blo.x;
            float v1 = sfull[nt][n8][1] * scale + blo.y;
            float v2 = sfull[nt][n8][2] * scale + bhi.x;
            float v3 = sfull[nt][n8][3] * scale + bhi.y;
            sfull[nt][n8][0] = v0; sfull[nt][n8][1] = v1;
            sfull[nt][n8][2] = v2; sfull[nt][n8][3] = v3;
            mx[0] = fmaxf(mx[0], fmaxf(v0, v1));
            mx[1] = fmaxf(mx[1], fmaxf(v2, v3));
        }
    #pragma unroll
    for (int o = 1; o <= 2; o <<= 1) {
        mx[0] = fmaxf(mx[0], __shfl_xor_sync(0xffffffffu, mx[0], o));
        mx[1] = fmaxf(mx[1], __shfl_xor_sync(0xffffffffu, mx[1], o));
    }
    float sum[2] = {0.f, 0.f};
    #pragma unroll
    for (int nt = 0; nt < 4; nt++)
        #pragma unroll
        for (int n8 = 0; n8 < 2; n8++)
            #pragma unroll
            for (int e = 0; e < 4; e++) {
                float ev = __expf(sfull[nt][n8][e] - mx[e >> 1]);
                sfull[nt][n8][e] = ev;
                sum[e >> 1] += ev;
            }
    #pragma unroll
    for (int o = 1; o <= 2; o <<= 1) {
        sum[0] += __shfl_xor_sync(0xffffffffu, sum[0], o);
        sum[1] += __shfl_xor_sync(0xffffffffu, sum[1], o);
    }
    float inv0 = 1.0f / sum[0], inv1 = 1.0f / sum[1];

    // ---- pack P fragments ----
    uint32_t pf[4][4];
    #pragma unroll
    for (int kt = 0; kt < 4; kt++) {
        __half2 h0 = __floats2half2_rn(sfull[kt][0][0] * inv0, sfull[kt][0][1] * inv0);
        __half2 h1 = __floats2half2_rn(sfull[kt][0][2] * inv1, sfull[kt][0][3] * inv1);
        __half2 h2 = __floats2half2_rn(sfull[kt][1][0] * inv0, sfull[kt][1][1] * inv0);
        __half2 h3 = __floats2half2_rn(sfull[kt][1][2] * inv1, sfull[kt][1][3] * inv1);
        pf[kt][0] = *(uint32_t*)&h0;
        pf[kt][1] = *(uint32_t*)&h1;
        pf[kt][2] = *(uint32_t*)&h2;
        pf[kt][3] = *(uint32_t*)&h3;
    }

    // ---- O = P V via ldmatrix.trans ----
    float co[2][2][4] = {};
    #pragma unroll
    for (int kt = 0; kt < 4; kt++) {
        #pragma unroll
        for (int nt = 0; nt < 2; nt++) {
            int row = kt * 16 + (lane & 7) + ((lane >> 3) & 1) * 8;
            int c8 = nt * 2 + (lane >> 4);
            uint32_t voff = row * 64 + ((c8 ^ (row & 3)) << 4);
            uint32_t bf[4];
            ldmx4t(bf, svb + voff);
            mma_f16(co[nt][0], pf[kt], bf[0], bf[1]);
            mma_f16(co[nt][1], pf[kt], bf[2], bf[3]);
        }
    }
    #pragma unroll
    for (int nt = 0; nt < 2; nt++)
        #pragma unroll
        for (int n8 = 0; n8 < 2; n8++)
            #pragma unroll
            for (int hf = 0; hf < 2; hf++) {
                int row = wid * 16 + r0 + hf * 8;
                if (row < NTOK) {
                    int col = nt * 16 + n8 * 8 + (lane & 3) * 2;
                    __half2 hv;
                    hv.x = __float2half_rn(co[nt][n8][hf * 2]);
                    hv.y = __float2half_rn(co[nt][n8][hf * 2 + 1]);
                    *(__half2*)(out + ((size_t)b * NTOK + row) * DIM + h * HD + col) = hv;
                }
            }
}

// ---------------------------------------------------------------------------
// Launch
// ---------------------------------------------------------------------------
extern "C" void kernel_launch(void* const* d_in, const int* in_sizes, int n_in,
                              void* d_out, int out_size)
{
    const float* x          = (const float*)d_in[0];
    const float* ln1_g      = (const float*)d_in[1];
    const float* ln1_b      = (const float*)d_in[2];
    const float* qkv_w      = (const float*)d_in[3];
    const float* proj_w     = (const float*)d_in[4];
    const float* proj_b     = (const float*)d_in[5];
    const float* bias_table = (const float*)d_in[6];
    const float* ln2_g      = (const float*)d_in[7];
    const float* ln2_b      = (const float*)d_in[8];
    const float* fc1_w      = (const float*)d_in[9];
    const float* fc1_b      = (const float*)d_in[10];
    const float* fc2_w      = (const float*)d_in[11];
    const float* fc2_b      = (const float*)d_in[12];
    const int*   rel_index  = (const int*)d_in[13];
    float* out = (float*)d_out;

    __half *act, *qkvh, *hid, *wq, *wp, *w1, *w2, *biasg;
    cudaGetSymbolAddress((void**)&act, g_act192);
    cudaGetSymbolAddress((void**)&qkvh, g_qkvh);
    cudaGetSymbolAddress((void**)&hid, g_hid);
    cudaGetSymbolAddress((void**)&wq, g_wqkv);
    cudaGetSymbolAddress((void**)&wp, g_wprj);
    cudaGetSymbolAddress((void**)&w1, g_wfc1);
    cudaGetSymbolAddress((void**)&w2, g_wfc2);
    cudaGetSymbolAddress((void**)&biasg, g_bias);

    cudaFuncSetAttribute(tc_gemm<576, 192, 0>, cudaFuncAttributeMaxDynamicSharedMemorySize, GEMM_SMEM);
    cudaFuncSetAttribute(tc_gemm<192, 192, 3>, cudaFuncAttributeMaxDynamicSharedMemorySize, GEMM_SMEM);
    cudaFuncSetAttribute(tc_gemm<768, 192, 2>, cudaFuncAttributeMaxDynamicSharedMemorySize, GEMM_SMEM);
    cudaFuncSetAttribute(tc_gemm<192, 768, 1>, cudaFuncAttributeMaxDynamicSharedMemorySize, GEMM_SMEM);

    // launch 1: all prep
    prep_all<<<894, 512>>>(qkv_w, wq, proj_w, wp, fc1_w, w1, fc2_w, w2,
                           bias_table, rel_index, biasg);
    // launch 2: LN1
    ln_kernel<<<MROWS / 8, 256>>>(x, ln1_g, ln1_b, act);
    // launch 3: qkv GEMM
    {
        dim3 grid(3, MROWS / 128);
        tc_gemm<576, 192, 0><<<grid, 512, GEMM_SMEM>>>(act, wq, nullptr, nullptr,
                                                       nullptr, qkvh, nullptr, nullptr);
    }
    // launch 4: attention
    attn_kernel<<<BW * HEADS, 128>>>(qkvh, biasg, act);
    // launch 5: proj + residual + fused LN2
    {
        dim3 grid(1, MROWS / 128);
        tc_gemm<192, 192, 3><<<grid, 512, GEMM_SMEM>>>(act, wp, proj_b, x,
                                                       out, act, ln2_g, ln2_b);
    }
    // launch 6: fc1 + GELU
    {
        dim3 grid(4, MROWS / 128);
        tc_gemm<768, 192, 2><<<grid, 512, GEMM_SMEM>>>(act, w1, fc1_b, nullptr,
                                                       nullptr, hid, nullptr, nullptr);
    }
    // launch 7: fc2 + residual
    {
        dim3 grid(1, MROWS / 128);
        tc_gemm<192, 768, 1><<<grid, 512, GEMM_SMEM>>>(hid, w2, fc2_b, out,
                                                       out, nullptr, nullptr, nullptr);
    }
}

// round 17
// speedup vs baseline: 1.9918x; 1.1246x over previous
#include <cuda_runtime.h>
#include <cuda_fp16.h>
#include <math.h>
#include <stdint.h>

#define BW    4096
#define NTOK  49
#define DIM   192
#define HEADS 6
#define HD    32
#define HIDDEN 768
#define MROWS (BW * NTOK)   // 200704

// ---------------------------------------------------------------------------
// Scratch (allocation-free, __device__ globals)
// ---------------------------------------------------------------------------
__device__ __half g_act192[(size_t)MROWS * DIM];
__device__ __half g_qkvh[(size_t)MROWS * 3 * DIM];
__device__ __half g_hid[(size_t)MROWS * HIDDEN];

__device__ __half g_wqkv[3 * DIM * DIM];
__device__ __half g_wprj[DIM * DIM];
__device__ __half g_wfc1[DIM * HIDDEN];
__device__ __half g_wfc2[HIDDEN * DIM];
__device__ __half g_bias[HEADS * 64 * 64];   // fp16 padded bias (64x64/head, -3e4 mask)

// ---------------------------------------------------------------------------
// helpers
// ---------------------------------------------------------------------------
__device__ __forceinline__ uint32_t smem_u32(const void* p) {
    uint32_t a;
    asm("{ .reg .u64 t; cvta.to.shared.u64 t, %1; cvt.u32.u64 %0, t; }" : "=r"(a) : "l"(p));
    return a;
}
__device__ __forceinline__ void cpa16(uint32_t dst, const void* src) {
    asm volatile("cp.async.cg.shared.global [%0], [%1], 16;" :: "r"(dst), "l"(src));
}
__device__ __forceinline__ void cp_commit() {
    asm volatile("cp.async.commit_group;" ::: "memory");
}
__device__ __forceinline__ void cp_wait1() {
    asm volatile("cp.async.wait_group 1;" ::: "memory");
}
__device__ __forceinline__ void ldmx4(uint32_t* r, uint32_t addr) {
    asm volatile("ldmatrix.sync.aligned.m8n8.x4.shared.b16 {%0,%1,%2,%3}, [%4];"
                 : "=r"(r[0]), "=r"(r[1]), "=r"(r[2]), "=r"(r[3]) : "r"(addr));
}
__device__ __forceinline__ void ldmx4t(uint32_t* r, uint32_t addr) {
    asm volatile("ldmatrix.sync.aligned.m8n8.x4.trans.shared.b16 {%0,%1,%2,%3}, [%4];"
                 : "=r"(r[0]), "=r"(r[1]), "=r"(r[2]), "=r"(r[3]) : "r"(addr));
}
__device__ __forceinline__ void mma_f16(float* c, const uint32_t* a,
                                        uint32_t b0, uint32_t b1) {
    asm volatile(
        "mma.sync.aligned.m16n8k16.row.col.f32.f16.f16.f32 "
        "{%0,%1,%2,%3}, {%4,%5,%6,%7}, {%8,%9}, {%0,%1,%2,%3};"
        : "+f"(c[0]), "+f"(c[1]), "+f"(c[2]), "+f"(c[3])
        : "r"(a[0]), "r"(a[1]), "r"(a[2]), "r"(a[3]), "r"(b0), "r"(b1));
}

// ---------------------------------------------------------------------------
// One merged prep kernel
// ---------------------------------------------------------------------------
#define PQ  (DIM * 576)
#define PP  (DIM * DIM)
#define P1  (DIM * HIDDEN)
#define P2  (HIDDEN * DIM)
#define PB  (HEADS * 64 * 64)
#define PTOT (PQ + PP + P1 + P2 + PB)

__global__ void prep_all(
    const float* __restrict__ Wq, __half* __restrict__ Wqt,
    const float* __restrict__ Wp, __half* __restrict__ Wpt,
    const float* __restrict__ W1, __half* __restrict__ W1t,
    const float* __restrict__ W2, __half* __restrict__ W2t,
    const float* __restrict__ table, const int* __restrict__ ridx,
    __half* __restrict__ biasg)
{
    for (int idx = blockIdx.x * blockDim.x + threadIdx.x; idx < PTOT;
         idx += gridDim.x * blockDim.x) {
        if (idx < PQ) {
            int k = idx / 576, n = idx - k * 576;
            Wqt[(size_t)n * DIM + k] = __float2half_rn(Wq[idx]);
        } else if (idx < PQ + PP) {
            int i = idx - PQ;
            int k = i / DIM, n = i - k * DIM;
            Wpt[(size_t)n * DIM + k] = __float2half_rn(Wp[i]);
        } else if (idx < PQ + PP + P1) {
            int i = idx - PQ - PP;
            int k = i / HIDDEN, n = i - k * HIDDEN;
            W1t[(size_t)n * DIM + k] = __float2half_rn(W1[i]);
        } else if (idx < PQ + PP + P1 + P2) {
            int i = idx - PQ - PP - P1;
            int k = i / DIM, n = i - k * DIM;
            W2t[(size_t)n * HIDDEN + k] = __float2half_rn(W2[i]);
        } else {
            int i = idx - PQ - PP - P1 - P2;
            int h = i >> 12, rc = i & 4095;
            int r = rc >> 6, c = rc & 63;
            float v = (r < NTOK && c < NTOK)
                      ? table[ridx[r * NTOK + c] * HEADS + h] : -30000.0f;
            biasg[i] = __float2half_rn(v);
        }
    }
}

// ---------------------------------------------------------------------------
// LayerNorm -> fp16: warp per row, 8 rows per 256-thread block, pure shfl.
// ---------------------------------------------------------------------------
__global__ __launch_bounds__(256) void ln_kernel(
    const float* __restrict__ x, const float* __restrict__ g,
    const float* __restrict__ b, __half* __restrict__ o)
{
    int row = blockIdx.x * 8 + (threadIdx.x >> 5);
    int lane = threadIdx.x & 31;
    const float* xp = x + (size_t)row * DIM;
    float v[6];
    float s = 0.f, s2 = 0.f;
    #pragma unroll
    for (int i = 0; i < 6; i++) {
        v[i] = xp[lane + 32 * i];
        s += v[i];
        s2 += v[i] * v[i];
    }
    #pragma unroll
    for (int of = 16; of > 0; of >>= 1) {
        s  += __shfl_xor_sync(0xffffffffu, s,  of);
        s2 += __shfl_xor_sync(0xffffffffu, s2, of);
    }
    float mu = s * (1.0f / DIM);
    float var = s2 * (1.0f / DIM) - mu * mu;
    float rstd = rsqrtf(var + 1e-5f);
    __half* op = o + (size_t)row * DIM;
    #pragma unroll
    for (int i = 0; i < 6; i++) {
        int c = lane + 32 * i;
        op[c] = __float2half_rn((v[i] - mu) * rstd * g[c] + b[c]);
    }
}

// ---------------------------------------------------------------------------
// fp16 HMMA GEMM: block tile 64x192, 256 threads = 8 warps (2 M x 4 N),
// warp tile 32x48 (same microkernel as before), 3-stage cp.async,
// __launch_bounds__(256,2) -> 2 CTAs/SM (independent sync domains).
// EPI: 0 -> fp16 | 1 bias+res -> fp32 | 2 bias+gelu -> fp16
//      3 bias+res -> fp32 + fused LN -> fp16 (N_TOTAL==192)
// ---------------------------------------------------------------------------
#define STAGE   16384u   // A 4K + B 12K
#define O_B     4096u
#define GEMM_SMEM (3 * 16384)

template <int N_TOTAL, int K_TOTAL, int EPI>
__global__ __launch_bounds__(256, 2) void tc_gemm(
    const __half* __restrict__ A, const __half* __restrict__ B,
    const float* __restrict__ bias, const float* __restrict__ res,
    float* __restrict__ Cf, __half* __restrict__ Ch,
    const float* __restrict__ lng, const float* __restrict__ lnb)
{
    constexpr int KSTEPS = K_TOTAL / 32;

    extern __shared__ char smem[];
    __shared__ float s_red[64 * 8];
    uint32_t sb = smem_u32(smem);
    int tid = threadIdx.x, lane = tid & 31, wid = tid >> 5;
    int wm = wid & 1, wn = wid >> 1;          // 2 x 4 warp grid
    size_t rowbase = (size_t)blockIdx.y * 64;
    int colbase = blockIdx.x * 192;

    auto load_stage = [&](int s) {
        uint32_t base = sb + (uint32_t)(s % 3) * STAGE;
        {   // A: 64 rows x 4 chunks = 256 -> 1 per thread
            int r = tid >> 2, kg = tid & 3;
            uint32_t soff = r * 64 + ((kg ^ (r & 3)) << 4);
            cpa16(base + soff, A + (rowbase + r) * K_TOTAL + s * 32 + kg * 8);
        }
        // B: 192 rows x 4 chunks = 768 -> 3 per thread
        #pragma unroll
        for (int j = 0; j < 3; j++) {
            int i = tid + j * 256;
            int r = i >> 2, kg = i & 3;
            uint32_t soff = r * 64 + ((kg ^ (r & 3)) << 4);
            cpa16(base + O_B + soff, B + (size_t)(colbase + r) * K_TOTAL + s * 32 + kg * 8);
        }
    };

    uint32_t aoff[2][2], boff[3][2];
    #pragma unroll
    for (int mt = 0; mt < 2; mt++)
        #pragma unroll
        for (int kk = 0; kk < 2; kk++) {
            int ra = wm * 32 + mt * 16 + (lane & 15);
            int kga = kk * 2 + (lane >> 4);
            aoff[mt][kk] = ra * 64 + ((kga ^ (ra & 3)) << 4);
        }
    #pragma unroll
    for (int np = 0; np < 3; np++)
        #pragma unroll
        for (int kk = 0; kk < 2; kk++) {
            int nb = wn * 48 + np * 16 + (lane & 7) + ((lane >> 4) << 3);
            int kgb = kk * 2 + ((lane >> 3) & 1);
            boff[np][kk] = nb * 64 + ((kgb ^ (nb & 3)) << 4);
        }

    float acc[2][6][4] = {};

    load_stage(0); cp_commit();
    load_stage(1); cp_commit();

    for (int s = 0; s < KSTEPS; s++) {
        cp_wait1();
        __syncthreads();
        if (s + 2 < KSTEPS) load_stage(s + 2);
        cp_commit();
        uint32_t base = sb + (uint32_t)(s % 3) * STAGE;
        #pragma unroll
        for (int kk = 0; kk < 2; kk++) {
            uint32_t ah[2][4];
            ldmx4(ah[0], base + aoff[0][kk]);
            ldmx4(ah[1], base + aoff[1][kk]);
            #pragma unroll
            for (int np = 0; np < 3; np++) {
                uint32_t bf[4];
                ldmx4(bf, base + O_B + boff[np][kk]);
                #pragma unroll
                for (int mt = 0; mt < 2; mt++) {
                    mma_f16(acc[mt][np * 2],     ah[mt], bf[0], bf[1]);
                    mma_f16(acc[mt][np * 2 + 1], ah[mt], bf[2], bf[3]);
                }
            }
        }
    }

    if (EPI == 3) {
        float psum[2][2] = {}, psq[2][2] = {};
        #pragma unroll
        for (int mt = 0; mt < 2; mt++)
            #pragma unroll
            for (int nt = 0; nt < 6; nt++) {
                int c = colbase + wn * 48 + nt * 8 + (lane & 3) * 2;
                #pragma unroll
                for (int half = 0; half < 2; half++) {
                    size_t row = rowbase + wm * 32 + mt * 16 + (lane >> 2) + half * 8;
                    float v0 = acc[mt][nt][half * 2]     + bias[c];
                    float v1 = acc[mt][nt][half * 2 + 1] + bias[c + 1];
                    const float2 rv = *(const float2*)(res + row * N_TOTAL + c);
                    v0 += rv.x; v1 += rv.y;
                    acc[mt][nt][half * 2] = v0;
                    acc[mt][nt][half * 2 + 1] = v1;
                    psum[mt][half] += v0 + v1;
                    psq[mt][half]  += v0 * v0 + v1 * v1;
                }
            }
        #pragma unroll
        for (int o = 1; o <= 2; o <<= 1)
            #pragma unroll
            for (int mt = 0; mt < 2; mt++)
                #pragma unroll
                for (int half = 0; half < 2; half++) {
                    psum[mt][half] += __shfl_xor_sync(0xffffffffu, psum[mt][half], o);
                    psq[mt][half]  += __shfl_xor_sync(0xffffffffu, psq[mt][half],  o);
                }
        if ((lane & 3) == 0) {
            #pragma unroll
            for (int mt = 0; mt < 2; mt++)
                #pragma unroll
                for (int half = 0; half < 2; half++) {
                    int lrow = wm * 32 + mt * 16 + (lane >> 2) + half * 8;
                    s_red[lrow * 8 + wn * 2]     = psum[mt][half];
                    s_red[lrow * 8 + wn * 2 + 1] = psq[mt][half];
                }
        }
        __syncthreads();
        float mu[2][2], rs[2][2];
        #pragma unroll
        for (int mt = 0; mt < 2; mt++)
            #pragma unroll
            for (int half = 0; half < 2; half++) {
                int lrow = wm * 32 + mt * 16 + (lane >> 2) + half * 8;
                float S = 0.f, Q = 0.f;
                #pragma unroll
                for (int w = 0; w < 4; w++) {
                    S += s_red[lrow * 8 + w * 2];
                    Q += s_red[lrow * 8 + w * 2 + 1];
                }
                float m = S * (1.0f / N_TOTAL);
                float var = Q * (1.0f / N_TOTAL) - m * m;
                mu[mt][half] = m;
                rs[mt][half] = rsqrtf(var + 1e-5f);
            }
        #pragma unroll
        for (int mt = 0; mt < 2; mt++)
            #pragma unroll
            for (int nt = 0; nt < 6; nt++) {
                int c = colbase + wn * 48 + nt * 8 + (lane & 3) * 2;
                float g0 = lng[c], g1 = lng[c + 1];
                float b0 = lnb[c], b1 = lnb[c + 1];
                #pragma unroll
                for (int half = 0; half < 2; half++) {
                    size_t row = rowbase + wm * 32 + mt * 16 + (lane >> 2) + half * 8;
                    float v0 = acc[mt][nt][half * 2];
                    float v1 = acc[mt][nt][half * 2 + 1];
                    float2 ov; ov.x = v0; ov.y = v1;
                    *(float2*)(Cf + row * N_TOTAL + c) = ov;
                    float n0 = (v0 - mu[mt][half]) * rs[mt][half] * g0 + b0;
                    float n1 = (v1 - mu[mt][half]) * rs[mt][half] * g1 + b1;
                    __half2 hv; hv.x = __float2half_rn(n0); hv.y = __float2half_rn(n1);
                    *(__half2*)(Ch + row * N_TOTAL + c) = hv;
                }
            }
    } else {
        #pragma unroll
        for (int mt = 0; mt < 2; mt++) {
            size_t rbase = rowbase + wm * 32 + mt * 16 + (lane >> 2);
            #pragma unroll
            for (int nt = 0; nt < 6; nt++) {
                int c = colbase + wn * 48 + nt * 8 + (lane & 3) * 2;
                #pragma unroll
                for (int half = 0; half < 2; half++) {
                    size_t row = rbase + half * 8;
                    float v0 = acc[mt][nt][half * 2];
                    float v1 = acc[mt][nt][half * 2 + 1];
                    if (EPI >= 1) { v0 += bias[c]; v1 += bias[c + 1]; }
                    if (EPI == 2) {
                        v0 = 0.5f * v0 * (1.0f + erff(v0 * 0.70710678118654752f));
                        v1 = 0.5f * v1 * (1.0f + erff(v1 * 0.70710678118654752f));
                    }
                    if (EPI == 1) {
                        const float2 rv = *(const float2*)(res + row * N_TOTAL + c);
                        float2 ov; ov.x = v0 + rv.x; ov.y = v1 + rv.y;
                        *(float2*)(Cf + row * N_TOTAL + c) = ov;
                    } else {
                        __half2 hv; hv.x = __float2half_rn(v0); hv.y = __float2half_rn(v1);
                        *(__half2*)(Ch + row * N_TOTAL + c) = hv;
                    }
                }
            }
        }
    }
}

// ---------------------------------------------------------------------------
// Tensor-core window attention (unchanged R14)
// ---------------------------------------------------------------------------
__global__ __launch_bounds__(128) void attn_kernel(
    const __half* __restrict__ qkv, const __half* __restrict__ bias,
    __half* __restrict__ out)
{
    int b = blockIdx.x / HEADS;
    int h = blockIdx.x % HEADS;
    int tid = threadIdx.x, lane = tid & 31, wid = tid >> 5;

    __shared__ __half sQ[64 * 32], sK[64 * 32], sV[64 * 32];
    __shared__ __half sBp[64 * 64];

    for (int i = tid; i < 256; i += 128) {
        ((uint4*)sQ)[i] = make_uint4(0, 0, 0, 0);
        ((uint4*)sK)[i] = make_uint4(0, 0, 0, 0);
        ((uint4*)sV)[i] = make_uint4(0, 0, 0, 0);
    }
    __syncthreads();

    const __half* base = qkv + (size_t)b * NTOK * (3 * DIM);
    for (int idx = tid; idx < NTOK * HD / 4; idx += 128) {
        int n = idx >> 3, dc = idx & 7;
        int d = dc * 4;
        const __half* tp = base + n * (3 * DIM) + h * HD + d;
        uint2 qv = *(const uint2*)tp;
        uint2 kv = *(const uint2*)(tp + DIM);
        uint2 vv = *(const uint2*)(tp + 2 * DIM);
        uint32_t off = n * 64 + ((((d >> 3) ^ (n & 3))) << 4) + (d & 7) * 2;
        *(uint2*)((char*)sQ + off) = qv;
        *(uint2*)((char*)sK + off) = kv;
        *(uint2*)((char*)sV + off) = vv;
    }
    {
        const uint4* bb = (const uint4*)(bias + (size_t)h * 64 * 64);
        #pragma unroll
        for (int j = 0; j < 4; j++) {
            int idx = tid + j * 128;
            int r = idx >> 3, c8 = idx & 7;
            uint32_t off = r * 128 + ((c8 ^ (r & 7)) << 4);
            *(uint4*)((char*)sBp + off) = bb[idx];
        }
    }
    __syncthreads();

    uint32_t sqb = smem_u32(sQ), skb = smem_u32(sK), svb = smem_u32(sV);
    uint32_t sbb = smem_u32(sBp);

    float sfull[4][2][4];
    {
        uint32_t a[2][4];
        #pragma unroll
        for (int kk = 0; kk < 2; kk++) {
            int ra = wid * 16 + (lane & 15);
            int kga = kk * 2 + (lane >> 4);
            ldmx4(a[kk], sqb + ra * 64 + ((kga ^ (ra & 3)) << 4));
        }
        #pragma unroll
        for (int nt = 0; nt < 4; nt++) {
            #pragma unroll
            for (int n8 = 0; n8 < 2; n8++)
                #pragma unroll
                for (int e = 0; e < 4; e++) sfull[nt][n8][e] = 0.f;
            #pragma unroll
            for (int kk = 0; kk < 2; kk++) {
                uint32_t bf[4];
                int nb = nt * 16 + (lane & 7) + ((lane >> 4) << 3);
                int kgb = kk * 2 + ((lane >> 3) & 1);
                ldmx4(bf, skb + nb * 64 + ((kgb ^ (nb & 3)) << 4));
                mma_f16(sfull[nt][0], a[kk], bf[0], bf[1]);
                mma_f16(sfull[nt][1], a[kk], bf[2], bf[3]);
            }
        }
    }

    uint32_t bfr[4][4];
    #pragma unroll
    for (int nt = 0; nt < 4; nt++) {
        int ra = wid * 16 + (lane & 15);
        int c8 = nt * 2 + (lane >> 4);
        ldmx4(bfr[nt], sbb + ra * 128 + ((c8 ^ (ra & 7)) << 4));
    }

    const float scale = 0.17677669529663687f;
    int r0 = lane >> 2;
    float mx[2] = {-1e30f, -1e30f};
    #pragma unroll
    for (int nt = 0; nt < 4; nt++)
        #pragma unroll
        for (int n8 = 0; n8 < 2; n8++) {
            float2 blo = __half22float2(*(__half2*)&bfr[nt][n8 * 2]);
            float2 bhi = __half22float2(*(__half2*)&bfr[nt][n8 * 2 + 1]);
            float v0 = sfull[nt][n8][0] * scale + blo.x;
            float v1 = sfull[nt][n8][1] * scale + blo.y;
            float v2 = sfull[nt][n8][2] * scale + bhi.x;
            float v3 = sfull[nt][n8][3] * scale + bhi.y;
            sfull[nt][n8][0] = v0; sfull[nt][n8][1] = v1;
            sfull[nt][n8][2] = v2; sfull[nt][n8][3] = v3;
            mx[0] = fmaxf(mx[0], fmaxf(v0, v1));
            mx[1] = fmaxf(mx[1], fmaxf(v2, v3));
        }
    #pragma unroll
    for (int o = 1; o <= 2; o <<= 1) {
        mx[0] = fmaxf(mx[0], __shfl_xor_sync(0xffffffffu, mx[0], o));
        mx[1] = fmaxf(mx[1], __shfl_xor_sync(0xffffffffu, mx[1], o));
    }
    float sum[2] = {0.f, 0.f};
    #pragma unroll
    for (int nt = 0; nt < 4; nt++)
        #pragma unroll
        for (int n8 = 0; n8 < 2; n8++)
            #pragma unroll
            for (int e = 0; e < 4; e++) {
                float ev = __expf(sfull[nt][n8][e] - mx[e >> 1]);
                sfull[nt][n8][e] = ev;
                sum[e >> 1] += ev;
            }
    #pragma unroll
    for (int o = 1; o <= 2; o <<= 1) {
        sum[0] += __shfl_xor_sync(0xffffffffu, sum[0], o);
        sum[1] += __shfl_xor_sync(0xffffffffu, sum[1], o);
    }
    float inv0 = 1.0f / sum[0], inv1 = 1.0f / sum[1];

    uint32_t pf[4][4];
    #pragma unroll
    for (int kt = 0; kt < 4; kt++) {
        __half2 h0 = __floats2half2_rn(sfull[kt][0][0] * inv0, sfull[kt][0][1] * inv0);
        __half2 h1 = __floats2half2_rn(sfull[kt][0][2] * inv1, sfull[kt][0][3] * inv1);
        __half2 h2 = __floats2half2_rn(sfull[kt][1][0] * inv0, sfull[kt][1][1] * inv0);
        __half2 h3 = __floats2half2_rn(sfull[kt][1][2] * inv1, sfull[kt][1][3] * inv1);
        pf[kt][0] = *(uint32_t*)&h0;
        pf[kt][1] = *(uint32_t*)&h1;
        pf[kt][2] = *(uint32_t*)&h2;
        pf[kt][3] = *(uint32_t*)&h3;
    }

    float co[2][2][4] = {};
    #pragma unroll
    for (int kt = 0; kt < 4; kt++) {
        #pragma unroll
        for (int nt = 0; nt < 2; nt++) {
            int row = kt * 16 + (lane & 7) + ((lane >> 3) & 1) * 8;
            int c8 = nt * 2 + (lane >> 4);
            uint32_t voff = row * 64 + ((c8 ^ (row & 3)) << 4);
            uint32_t bf[4];
            ldmx4t(bf, svb + voff);
            mma_f16(co[nt][0], pf[kt], bf[0], bf[1]);
            mma_f16(co[nt][1], pf[kt], bf[2], bf[3]);
        }
    }
    #pragma unroll
    for (int nt = 0; nt < 2; nt++)
        #pragma unroll
        for (int n8 = 0; n8 < 2; n8++)
            #pragma unroll
            for (int hf = 0; hf < 2; hf++) {
                int row = wid * 16 + r0 + hf * 8;
                if (row < NTOK) {
                    int col = nt * 16 + n8 * 8 + (lane & 3) * 2;
                    __half2 hv;
                    hv.x = __float2half_rn(co[nt][n8][hf * 2]);
                    hv.y = __float2half_rn(co[nt][n8][hf * 2 + 1]);
                    *(__half2*)(out + ((size_t)b * NTOK + row) * DIM + h * HD + col) = hv;
                }
            }
}

// ---------------------------------------------------------------------------
// Launch
// ---------------------------------------------------------------------------
extern "C" void kernel_launch(void* const* d_in, const int* in_sizes, int n_in,
                              void* d_out, int out_size)
{
    const float* x          = (const float*)d_in[0];
    const float* ln1_g      = (const float*)d_in[1];
    const float* ln1_b      = (const float*)d_in[2];
    const float* qkv_w      = (const float*)d_in[3];
    const float* proj_w     = (const float*)d_in[4];
    const float* proj_b     = (const float*)d_in[5];
    const float* bias_table = (const float*)d_in[6];
    const float* ln2_g      = (const float*)d_in[7];
    const float* ln2_b      = (const float*)d_in[8];
    const float* fc1_w      = (const float*)d_in[9];
    const float* fc1_b      = (const float*)d_in[10];
    const float* fc2_w      = (const float*)d_in[11];
    const float* fc2_b      = (const float*)d_in[12];
    const int*   rel_index  = (const int*)d_in[13];
    float* out = (float*)d_out;

    __half *act, *qkvh, *hid, *wq, *wp, *w1, *w2, *biasg;
    cudaGetSymbolAddress((void**)&act, g_act192);
    cudaGetSymbolAddress((void**)&qkvh, g_qkvh);
    cudaGetSymbolAddress((void**)&hid, g_hid);
    cudaGetSymbolAddress((void**)&wq, g_wqkv);
    cudaGetSymbolAddress((void**)&wp, g_wprj);
    cudaGetSymbolAddress((void**)&w1, g_wfc1);
    cudaGetSymbolAddress((void**)&w2, g_wfc2);
    cudaGetSymbolAddress((void**)&biasg, g_bias);

    cudaFuncSetAttribute(tc_gemm<576, 192, 0>, cudaFuncAttributeMaxDynamicSharedMemorySize, GEMM_SMEM);
    cudaFuncSetAttribute(tc_gemm<192, 192, 3>, cudaFuncAttributeMaxDynamicSharedMemorySize, GEMM_SMEM);
    cudaFuncSetAttribute(tc_gemm<768, 192, 2>, cudaFuncAttributeMaxDynamicSharedMemorySize, GEMM_SMEM);
    cudaFuncSetAttribute(tc_gemm<192, 768, 1>, cudaFuncAttributeMaxDynamicSharedMemorySize, GEMM_SMEM);

    // launch 1: all prep
    prep_all<<<894, 512>>>(qkv_w, wq, proj_w, wp, fc1_w, w1, fc2_w, w2,
                           bias_table, rel_index, biasg);
    // launch 2: LN1
    ln_kernel<<<MROWS / 8, 256>>>(x, ln1_g, ln1_b, act);
    // launch 3: qkv GEMM
    {
        dim3 grid(3, MROWS / 64);
        tc_gemm<576, 192, 0><<<grid, 256, GEMM_SMEM>>>(act, wq, nullptr, nullptr,
                                                       nullptr, qkvh, nullptr, nullptr);
    }
    // launch 4: attention
    attn_kernel<<<BW * HEADS, 128>>>(qkvh, biasg, act);
    // launch 5: proj + residual + fused LN2
    {
        dim3 grid(1, MROWS / 64);
        tc_gemm<192, 192, 3><<<grid, 256, GEMM_SMEM>>>(act, wp, proj_b, x,
                                                       out, act, ln2_g, ln2_b);
    }
    // launch 6: fc1 + GELU
    {
        dim3 grid(4, MROWS / 64);
        tc_gemm<768, 192, 2><<<grid, 256, GEMM_SMEM>>>(act, w1, fc1_b, nullptr,
                                                       nullptr, hid, nullptr, nullptr);
    }
    // launch 7: fc2 + residual
    {
        dim3 grid(1, MROWS / 64);
        tc_gemm<192, 768, 1><<<grid, 256, GEMM_SMEM>>>(hid, w2, fc2_b, out,
                                                       out, nullptr, nullptr, nullptr);
    }
}